// round 13
// baseline (speedup 1.0000x reference)
#include <cuda_runtime.h>
#include <cuda_bf16.h>
#include <cstdint>

#define BB 128
#define TT 100
#define NN 2048
#define OO 512
#define DLY 10

#define ALPHA_F   0.90483741803595957316f   // exp(-1/10)
#define DEC_F     0.95122942450071400910f   // exp(-1/20)
#define CDEC_F    0.04877057549928599090f   // 1 - exp(-1/20)
#define THRESH_F  0.02f
#define A_PLUS_F  1e-4f
#define A_MINUS_F 1e-4f
#define INVB_F    0.0078125f                // 1/128, exact

#define SPLIT_A 16
#define SPLIT_I 4

typedef __nv_bfloat16 bf16;

// ---------------- state ----------------
__device__ uint32_t g_spk[(size_t)TT*BB*64];        // l1 spikes as bits (3.2MB)
__device__ float g_t1f[BB*NN];                      // rolling tr1 fp32
__device__ bf16  g_t1h[BB*NN], g_t1l[BB*NN];        // rolling tr1 splits
__device__ float g_v2 [BB*OO];
__device__ float g_vi [BB*OO];
__device__ float g_tr2[BB*OO];
__device__ float g_tri[BB*OO];
__device__ bf16  g_tr2h[BB*OO], g_tr2l[BB*OO];
__device__ bf16  g_trih[BB*OO], g_tril[BB*OO];
__device__ bf16  g_bufb[BB*DLY*OO];
__device__ float g_hw [(size_t)OO*NN];
__device__ float g_iew[OO*OO];
__device__ float g_ediag[OO];
__device__ float g_mtr2[OO];
__device__ float g_pA[SPLIT_A*BB*OO];
__device__ float g_pI[SPLIT_I*BB*OO];
__device__ int   g_nzcnt[NN];
__device__ int   g_nzcol[(size_t)NN*NN];
__device__ float g_nzval[(size_t)NN*NN];
__device__ int   g_qdone[8];                        // per-64q-tile gemm-done counters

__device__ __forceinline__ void split3(float w, bf16& h, bf16& m, bf16& l) {
    h = __float2bfloat16(w);
    float r1 = __fadd_rn(w, -__bfloat162float(h));
    m = __float2bfloat16(r1);
    float r2 = __fadd_rn(r1, -__bfloat162float(m));
    l = __float2bfloat16(r2);
}
__device__ __forceinline__ void split2(float w, bf16& h, bf16& l) {
    h = __float2bfloat16(w);
    l = __float2bfloat16(__fadd_rn(w, -__bfloat162float(h)));
}
__device__ __forceinline__ uint32_t s2u(const void* p) {
    return (uint32_t)__cvta_generic_to_shared(p);
}
__device__ __forceinline__ void cpa16(uint32_t d, const void* s) {
    asm volatile("cp.async.ca.shared.global [%0], [%1], 16;\n" :: "r"(d), "l"(s));
}
__device__ __forceinline__ void cpa_commit() {
    asm volatile("cp.async.commit_group;\n");
}
__device__ __forceinline__ void cpa_wait_all() {
    asm volatile("cp.async.wait_group 0;\n");
}
__device__ __forceinline__ uint32_t packbf2(bf16 a, bf16 b) {
    __nv_bfloat162 v(a, b);
    return *(uint32_t*)&v;
}

// ---------------- init ----------------
__global__ void k_init(const float* __restrict__ hw_in,
                       const float* __restrict__ eiw_in,
                       const float* __restrict__ iew_in) {
    int i = blockIdx.x * blockDim.x + threadIdx.x;
    if (i < OO*NN) g_hw[i] = hw_in[i];
    if (i < BB*NN) {
        g_t1f[i] = 0.f;
        bf16 z = __float2bfloat16(0.f);
        g_t1h[i] = z; g_t1l[i] = z;
    }
    if (i < BB*DLY*OO) g_bufb[i] = __float2bfloat16(0.f);
    if (i < BB*OO) {
        g_v2[i]=0.f; g_vi[i]=0.f; g_tr2[i]=0.f; g_tri[i]=0.f;
        bf16 z = __float2bfloat16(0.f);
        g_tr2h[i]=z; g_tr2l[i]=z; g_trih[i]=z; g_tril[i]=z;
    }
    if (i < OO*OO) {
        int r = i / OO, c = i - r*OO;
        g_iew[i] = (r == c) ? 0.f : iew_in[i];
    }
    if (i < OO) g_ediag[i] = eiw_in[i*OO + i];
    if (i < 8) g_qdone[i] = 0;
}

// ---------------- CSR build ----------------
__global__ void k_csr(const float* __restrict__ W) {
    int wid  = (blockIdx.x * blockDim.x + threadIdx.x) >> 5;
    int lane = threadIdx.x & 31;
    if (wid >= NN) return;
    int cnt = 0;
    for (int base = 0; base < NN; base += 32) {
        float w = W[wid*NN + base + lane];
        unsigned m = __ballot_sync(0xffffffffu, w != 0.f);
        if (w != 0.f) {
            int pos = cnt + __popc(m & ((1u << lane) - 1u));
            g_nzcol[(size_t)wid*NN + pos] = base + lane;
            g_nzval[(size_t)wid*NN + pos] = w;
        }
        cnt += __popc(m);
    }
    if (lane == 0) g_nzcnt[wid] = cnt;
}

// ---------------- layer 1: all T steps, spikes -> fp32 out + bitmask ----------------
__global__ __launch_bounds__(256) void k_layer1_all(const float* __restrict__ x,
                                                    float* __restrict__ out_l1) {
    int idx = blockIdx.x * 256 + threadIdx.x;
    int b = idx >> 11;
    int n = idx & (NN - 1);
    int cnt = g_nzcnt[n];
    const int*   cp = g_nzcol + (size_t)n*NN;
    const float* vp = g_nzval + (size_t)n*NN;
    const float* xb = x + (size_t)b*TT*NN;
    float v = 0.f;
    for (int t = 0; t < TT; t++) {
        const float* xr = xb + (size_t)t*NN;
        float acc = 0.f;
        for (int j = 0; j < cnt; j++) acc = fmaf(xr[cp[j]], vp[j], acc);
        v = fmaf(ALPHA_F, v, acc);
        float s = (v > THRESH_F) ? 1.f : 0.f;
        v = (v > THRESH_F) ? 0.f : v;
        out_l1[((size_t)b*TT + t)*NN + n] = s;
        unsigned m = __ballot_sync(0xffffffffu, s > 0.f);
        if ((n & 31) == 0) g_spk[((size_t)t*BB + b)*64 + (n >> 5)] = m;
    }
}

extern __shared__ __align__(16) char smem_raw[];

// ---------------- epi item (R8-identical math; item 0..63 covers 8 q) ----------------
__device__ __forceinline__ void epi_item(int item, float* __restrict__ out_l2, int t, int tm) {
    __shared__ float sh[3][32][8];
    int qb = item * 8;
    int tq = threadIdx.x & 7;
    int tb = threadIdx.x >> 3;
    int q  = qb + tq;

    float r2 = 0.f, ri = 0.f, rd = 0.f;
    for (int j = 0; j < 4; j++) {
        int b  = tb + 32*j;
        int bo = b*OO + q;
        float l1v = 0.f, io = 0.f;
        #pragma unroll
        for (int s = 0; s < SPLIT_A; s++) l1v = __fadd_rn(l1v, g_pA[(size_t)s*BB*OO + bo]);
        #pragma unroll
        for (int s = 0; s < SPLIT_I; s++) io  = __fadd_rn(io,  g_pI[(size_t)s*BB*OO + bo]);
        float v = fmaf(ALPHA_F, g_v2[bo], __fadd_rn(l1v, -io));
        float s2 = (v > THRESH_F) ? 1.f : 0.f;
        g_v2[bo] = (v > THRESH_F) ? 0.f : v;
        out_l2[((size_t)b*TT + t)*OO + q] = s2;
        float t2 = fmaf(DEC_F, g_tr2[bo], __fmul_rn(CDEC_F, s2));
        g_tr2[bo] = t2;
        { bf16 h, l; split2(t2, h, l); g_tr2h[bo] = h; g_tr2l[bo] = l; }
        float inh_in = __fmul_rn(s2, g_ediag[q]);
        float vv = fmaf(ALPHA_F, g_vi[bo], inh_in);
        float si = (vv > THRESH_F) ? 1.f : 0.f;
        g_vi[bo] = (vv > THRESH_F) ? 0.f : vv;
        g_bufb[((size_t)b*DLY + tm)*OO + q] = __float2bfloat16(si);
        float ti = fmaf(DEC_F, g_tri[bo], __fmul_rn(CDEC_F, si));
        g_tri[bo] = ti;
        { bf16 h, l; split2(ti, h, l); g_trih[bo] = h; g_tril[bo] = l; }
        r2 += t2; ri += ti; rd = fmaf(ti, t2, rd);
    }
    sh[0][tb][tq] = r2; sh[1][tb][tq] = ri; sh[2][tb][tq] = rd;
    __syncthreads();
    if (tb == 0) {
        float s2 = 0.f, si = 0.f, sd = 0.f;
        for (int g = 0; g < 32; g++) { s2 += sh[0][g][tq]; si += sh[1][g][tq]; sd += sh[2][g][tq]; }
        float m2 = s2 * INVB_F, mi = si * INVB_F;
        g_mtr2[q] = m2;
        float e = g_ediag[q];
        float dw = fmaf(A_PLUS_F, __fmul_rn(sd, INVB_F),
                        -__fmul_rn(__fmul_rn(A_MINUS_F, e), mi));
        g_ediag[q] = __fadd_rn(e, dw);
    }
}

// ---------------- launch A: gemm items 0..319 (signal) + epi blocks 320..383 (wait) ----------------
__global__ __launch_bounds__(256) void k_gemm(float* __restrict__ out_l2, int t, int tm) {
    int bid = blockIdx.x;
    int tid = threadIdx.x;

    if (bid >= 320) {
        // dataflow-gated epilogue: wait for all 40 gemm items of this q-tile group
        int item = bid - 320;                // 0..63
        if (tid == 0) {
            while (*((volatile int*)&g_qdone[item >> 3]) < 40) __nanosleep(64);
            __threadfence();
        }
        __syncthreads();
        epi_item(item, out_l2, t, tm);
        return;
    }

    bf16* sA = (bf16*)smem_raw;        // [64][136]
    bf16* sB = sA + 64*136;            // [3][64][136]
    int item = bid;
    int chunk = item >> 4, qt = item & 7, mo = ((item >> 3) & 1) * 64;
    const float* Wf;
    int wstride, k0; float* part;
    uint32_t sAu = s2u(sA), sBu = s2u(sB);
    int q0 = qt*64;

    if (chunk < SPLIT_A) {
        k0 = chunk*128;
        Wf = g_hw; wstride = NN;
        part = g_pA + (size_t)chunk*BB*OO;
        // decode spike bits -> bf16 tile [64][128]
        int r = tid >> 2, wsel = tid & 3;
        uint32_t wbits = g_spk[((size_t)t*BB + mo + r)*64 + (k0 >> 5) + wsel];
        uint32_t* dst = (uint32_t*)(sA + r*136 + wsel*32);
        #pragma unroll
        for (int i = 0; i < 16; i++) {
            uint32_t v = (((wbits >> (2*i)) & 1u) ? 0x3F80u : 0u)
                       | (((wbits >> (2*i+1)) & 1u) ? 0x3F800000u : 0u);
            dst[i] = v;
        }
    } else {
        k0 = (chunk - SPLIT_A)*128;
        Wf = g_iew; wstride = OO;
        part = g_pI + (size_t)(chunk - SPLIT_A)*BB*OO;
        const bf16* Asrc = g_bufb + tm*OO;
        #pragma unroll
        for (int i = 0; i < 4; i++) {
            int idx = tid + i*256;
            int r = idx >> 4, c8 = idx & 15;
            cpa16(sAu + (uint32_t)(r*136 + c8*8)*2u,
                  Asrc + (size_t)(mo + r)*((size_t)DLY*OO) + k0 + c8*8);
        }
        cpa_commit();
    }

    // weight fp32 load + in-register 3-way split -> sB[3] tiles
    {
        int r = tid >> 2, cb = (tid & 3) * 32;
        const float* wrow = Wf + (size_t)(q0 + r)*wstride + k0 + cb;
        bf16* sh_ = sB + r*136 + cb;
        bf16* sm_ = sB + (64 + r)*136 + cb;
        bf16* sl_ = sB + (128 + r)*136 + cb;
        #pragma unroll
        for (int i = 0; i < 8; i++) {
            float4 wv = *(const float4*)(wrow + i*4);
            bf16 h0,m0,l0,h1,m1,l1,h2,m2,l2,h3,m3,l3;
            split3(wv.x, h0, m0, l0);
            split3(wv.y, h1, m1, l1);
            split3(wv.z, h2, m2, l2);
            split3(wv.w, h3, m3, l3);
            *(uint32_t*)(sh_ + i*4)     = packbf2(h0, h1);
            *(uint32_t*)(sh_ + i*4 + 2) = packbf2(h2, h3);
            *(uint32_t*)(sm_ + i*4)     = packbf2(m0, m1);
            *(uint32_t*)(sm_ + i*4 + 2) = packbf2(m2, m3);
            *(uint32_t*)(sl_ + i*4)     = packbf2(l0, l1);
            *(uint32_t*)(sl_ + i*4 + 2) = packbf2(l2, l3);
        }
    }
    if (chunk >= SPLIT_A) cpa_wait_all();
    __syncthreads();

    int w = tid >> 5, lane = tid & 31, g = lane >> 2, qi = lane & 3;
    int wm = w & 3, wn = w >> 2;
    int lr = lane & 7, lsel = lane >> 3;

    uint32_t a[8][4];
    int arow = 16*wm + lr + ((lsel & 1) ? 8 : 0);
    #pragma unroll
    for (int k16 = 0; k16 < 8; k16++) {
        int acol = k16*16 + ((lsel & 2) ? 8 : 0);
        uint32_t addr = sAu + (uint32_t)(arow*136 + acol)*2u;
        asm volatile("ldmatrix.sync.aligned.m8n8.x4.shared.b16 {%0,%1,%2,%3}, [%4];"
                     : "=r"(a[k16][0]), "=r"(a[k16][1]), "=r"(a[k16][2]), "=r"(a[k16][3])
                     : "r"(addr));
    }

    float acc[4][4];
    #pragma unroll
    for (int j = 0; j < 4; j++) { acc[j][0]=0.f; acc[j][1]=0.f; acc[j][2]=0.f; acc[j][3]=0.f; }

    int brow_base = wn*32 + lr;
    int bcol_off = (lane & 8) ? 8 : 0;
    #pragma unroll
    for (int s = 0; s < 3; s++) {
        #pragma unroll
        for (int k16 = 0; k16 < 8; k16++) {
            uint32_t bb[4][2];
            #pragma unroll
            for (int j = 0; j < 4; j++) {
                uint32_t baddr = sBu + (uint32_t)((s*64 + brow_base + j*8)*136 + k16*16 + bcol_off)*2u;
                asm volatile("ldmatrix.sync.aligned.m8n8.x2.shared.b16 {%0,%1}, [%2];"
                             : "=r"(bb[j][0]), "=r"(bb[j][1]) : "r"(baddr));
            }
            #pragma unroll
            for (int j = 0; j < 4; j++) {
                asm volatile(
                    "mma.sync.aligned.m16n8k16.row.col.f32.bf16.bf16.f32 "
                    "{%0,%1,%2,%3},{%4,%5,%6,%7},{%8,%9},{%0,%1,%2,%3};\n"
                    : "+f"(acc[j][0]), "+f"(acc[j][1]), "+f"(acc[j][2]), "+f"(acc[j][3])
                    : "r"(a[k16][0]), "r"(a[k16][1]), "r"(a[k16][2]), "r"(a[k16][3]),
                      "r"(bb[j][0]), "r"(bb[j][1]));
            }
        }
    }
    int m0 = mo + 16*wm + g;
    #pragma unroll
    for (int j = 0; j < 4; j++) {
        int qc = q0 + wn*32 + j*8 + qi*2;
        *(float2*)(part + (size_t)m0*OO + qc)       = make_float2(acc[j][0], acc[j][1]);
        *(float2*)(part + (size_t)(m0 + 8)*OO + qc) = make_float2(acc[j][2], acc[j][3]);
    }

    // signal completion for this q-tile, then do tr1 tail
    __syncthreads();
    if (tid == 0) { __threadfence(); atomicAdd(&g_qdone[qt], 1); }

    // ---- tr1 rolling update tail: blocks 0..255, 1024 elements each, vectorized ----
    if (bid < 256) {
        int base = bid*1024 + tid*4;
        int b = base >> 11, n = base & (NN - 1);
        uint32_t wbits = g_spk[((size_t)t*BB + b)*64 + (n >> 5)];
        int sh = n & 31;
        float4 tr = *(float4*)(g_t1f + base);
        float s0 = ((wbits >> (sh+0)) & 1u) ? 1.f : 0.f;
        float s1 = ((wbits >> (sh+1)) & 1u) ? 1.f : 0.f;
        float s2 = ((wbits >> (sh+2)) & 1u) ? 1.f : 0.f;
        float s3 = ((wbits >> (sh+3)) & 1u) ? 1.f : 0.f;
        tr.x = fmaf(DEC_F, tr.x, __fmul_rn(CDEC_F, s0));
        tr.y = fmaf(DEC_F, tr.y, __fmul_rn(CDEC_F, s1));
        tr.z = fmaf(DEC_F, tr.z, __fmul_rn(CDEC_F, s2));
        tr.w = fmaf(DEC_F, tr.w, __fmul_rn(CDEC_F, s3));
        *(float4*)(g_t1f + base) = tr;
        bf16 h0,l0,h1,l1,h2,l2,h3,l3;
        split2(tr.x, h0, l0); split2(tr.y, h1, l1);
        split2(tr.z, h2, l2); split2(tr.w, h3, l3);
        *(uint2*)(g_t1h + base) = make_uint2(packbf2(h0, h1), packbf2(h2, h3));
        *(uint2*)(g_t1l + base) = make_uint2(packbf2(l0, l1), packbf2(l2, l3));
    }
}

// ---------------- launch B: plast only (no wait, fp32 weight store only) ----------------
__global__ __launch_bounds__(256) void k_plast() {
    int bx = blockIdx.x, by = blockIdx.y;
    int tid = threadIdx.x;
    if (bx == 0 && by == 0 && tid < 8) g_qdone[tid] = 0;   // reset for next step's gemm

    bf16* sAh = (bf16*)smem_raw;        // [b=128][72] (tr2 hi)
    bf16* sAl = sAh + 128*72;
    bf16* sB0 = sAl + 128*72;           // [b=128][72] (pre hi)
    bf16* sB1 = sB0 + 128*72;
    int mode = (bx >= 32);
    int p0 = (mode ? (bx - 32) : bx) * 64;
    int q0 = by * 64;
    const bf16* preh = mode ? g_trih : g_t1h;
    const bf16* prel = mode ? g_tril : g_t1l;
    int P = mode ? OO : NN;
    float* W = mode ? g_iew : g_hw;

    uint32_t sAhu = s2u(sAh), sAlu = s2u(sAl), sB0u = s2u(sB0), sB1u = s2u(sB1);

    #pragma unroll
    for (int i = 0; i < 4; i++) {
        int idx = tid + i*256;
        int b = idx >> 3, c8 = idx & 7;
        uint32_t so = (uint32_t)(b*72 + c8*8)*2u;
        cpa16(sAhu + so, g_tr2h + b*OO + q0 + c8*8);
        cpa16(sAlu + so, g_tr2l + b*OO + q0 + c8*8);
        cpa16(sB0u + so, preh + (size_t)b*P + p0 + c8*8);
        cpa16(sB1u + so, prel + (size_t)b*P + p0 + c8*8);
    }
    cpa_commit();
    cpa_wait_all();
    __syncthreads();

    int w = tid >> 5, lane = tid & 31, g = lane >> 2, qi = lane & 3;
    int r8 = lane & 7, sel = lane >> 3;

    float acc[4][4];
    #pragma unroll
    for (int mi = 0; mi < 4; mi++) { acc[mi][0]=0.f; acc[mi][1]=0.f; acc[mi][2]=0.f; acc[mi][3]=0.f; }

    #pragma unroll
    for (int k16 = 0; k16 < 8; k16++) {
        int kb16 = k16*16;
        int rrB = kb16 + ((sel & 1) ? 8 : 0) + r8;
        uint32_t bo = (uint32_t)(rrB*72 + w*8)*2u;
        uint32_t bh0, bh1, bl0, bl1;
        asm volatile("ldmatrix.sync.aligned.m8n8.x2.trans.shared.b16 {%0,%1}, [%2];"
                     : "=r"(bh0), "=r"(bh1) : "r"(sB0u + bo));
        asm volatile("ldmatrix.sync.aligned.m8n8.x2.trans.shared.b16 {%0,%1}, [%2];"
                     : "=r"(bl0), "=r"(bl1) : "r"(sB1u + bo));
        int rrA = kb16 + ((sel & 2) ? 8 : 0) + r8;
        #pragma unroll
        for (int mi = 0; mi < 4; mi++) {
            int cc = mi*16 + ((sel & 1) ? 8 : 0);
            uint32_t ao = (uint32_t)(rrA*72 + cc)*2u;
            #pragma unroll
            for (int as = 0; as < 2; as++) {
                uint32_t a0, a1, a2, a3;
                asm volatile("ldmatrix.sync.aligned.m8n8.x4.trans.shared.b16 {%0,%1,%2,%3}, [%4];"
                             : "=r"(a0), "=r"(a1), "=r"(a2), "=r"(a3)
                             : "r"((as ? sAlu : sAhu) + ao));
                asm volatile(
                    "mma.sync.aligned.m16n8k16.row.col.f32.bf16.bf16.f32 "
                    "{%0,%1,%2,%3},{%4,%5,%6,%7},{%8,%9},{%0,%1,%2,%3};\n"
                    : "+f"(acc[mi][0]), "+f"(acc[mi][1]), "+f"(acc[mi][2]), "+f"(acc[mi][3])
                    : "r"(a0), "r"(a1), "r"(a2), "r"(a3), "r"(bh0), "r"(bh1));
                asm volatile(
                    "mma.sync.aligned.m16n8k16.row.col.f32.bf16.bf16.f32 "
                    "{%0,%1,%2,%3},{%4,%5,%6,%7},{%8,%9},{%0,%1,%2,%3};\n"
                    : "+f"(acc[mi][0]), "+f"(acc[mi][1]), "+f"(acc[mi][2]), "+f"(acc[mi][3])
                    : "r"(a0), "r"(a1), "r"(a2), "r"(a3), "r"(bl0), "r"(bl1));
            }
        }
    }

    int pc = p0 + w*8 + qi*2;
    #pragma unroll
    for (int mi = 0; mi < 4; mi++) {
        #pragma unroll
        for (int half = 0; half < 2; half++) {
            int qq = q0 + mi*16 + g + half*8;
            float h0 = acc[mi][half*2 + 0], h1 = acc[mi][half*2 + 1];
            float mean = g_mtr2[qq];
            size_t wbase = (size_t)qq*P + pc;
            float2 wv = *(float2*)(W + wbase);
            float dw0 = fmaf(A_PLUS_F, __fmul_rn(h0, INVB_F),
                             -__fmul_rn(__fmul_rn(A_MINUS_F, wv.x), mean));
            float dw1 = fmaf(A_PLUS_F, __fmul_rn(h1, INVB_F),
                             -__fmul_rn(__fmul_rn(A_MINUS_F, wv.y), mean));
            float nw0 = __fadd_rn(wv.x, dw0);
            float nw1 = __fadd_rn(wv.y, dw1);
            if (mode && qq == pc)     nw0 = 0.f;
            if (mode && qq == pc + 1) nw1 = 0.f;
            *(float2*)(W + wbase) = make_float2(nw0, nw1);
        }
    }
}

// ---------------- launch ----------------
extern "C" void kernel_launch(void* const* d_in, const int* in_sizes, int n_in,
                              void* d_out, int out_size) {
    const float* x      = (const float*)d_in[0];
    const float* win    = (const float*)d_in[1];
    const float* hw_in  = (const float*)d_in[2];
    const float* eiw_in = (const float*)d_in[3];
    const float* iew_in = (const float*)d_in[4];
    float* out_l1 = (float*)d_out;
    float* out_l2 = out_l1 + (size_t)BB*TT*NN;

    const int sm_gemm  = 4 * 64*136 * 2;   // 69632
    const int sm_plast = 4 * 128*72 * 2;   // 73728
    cudaFuncSetAttribute(k_gemm,  cudaFuncAttributeMaxDynamicSharedMemorySize, sm_gemm);
    cudaFuncSetAttribute(k_plast, cudaFuncAttributeMaxDynamicSharedMemorySize, sm_plast);

    k_init<<<(OO*NN)/256, 256>>>(hw_in, eiw_in, iew_in);
    k_csr<<<256, 256>>>(win);
    k_layer1_all<<<(BB*NN)/256, 256>>>(x, out_l1);

    for (int t = 0; t < TT; t++) {
        int tm = t % DLY;
        k_gemm<<<384, 256, sm_gemm>>>(out_l2, t, tm);
        k_plast<<<dim3(40, 8), 256, sm_plast>>>();
    }
}

// round 14
// speedup vs baseline: 1.0308x; 1.0308x over previous
#include <cuda_runtime.h>
#include <cuda_bf16.h>
#include <cstdint>

#define BB 128
#define TT 100
#define NN 2048
#define OO 512
#define DLY 10

#define ALPHA_F   0.90483741803595957316f   // exp(-1/10)
#define DEC_F     0.95122942450071400910f   // exp(-1/20)
#define CDEC_F    0.04877057549928599090f   // 1 - exp(-1/20)
#define THRESH_F  0.02f
#define A_PLUS_F  1e-4f
#define A_MINUS_F 1e-4f
#define INVB_F    0.0078125f                // 1/128, exact

#define SPLIT_A 16
#define SPLIT_I 4

typedef __nv_bfloat16 bf16;

// ---------------- state ----------------
__device__ uint32_t g_spk[(size_t)TT*BB*64];        // l1 spikes as bits (3.2MB)
__device__ float g_t1f[BB*NN];                      // rolling tr1 fp32
__device__ bf16  g_t1h[BB*NN], g_t1l[BB*NN];        // rolling tr1 splits
__device__ float g_v2 [BB*OO];
__device__ float g_vi [BB*OO];
__device__ float g_tr2[BB*OO];
__device__ float g_tri[BB*OO];
__device__ bf16  g_tr2h[BB*OO], g_tr2l[BB*OO];
__device__ bf16  g_trih[BB*OO], g_tril[BB*OO];
__device__ bf16  g_bufb[BB*DLY*OO];
__device__ float g_hw [(size_t)OO*NN];
__device__ bf16  g_hwh[(size_t)OO*NN], g_hwm[(size_t)OO*NN], g_hwl[(size_t)OO*NN];
__device__ float g_iew[OO*OO];
__device__ bf16  g_iewh[OO*OO], g_iewm[OO*OO], g_iewl[OO*OO];
__device__ float g_ediag[OO];
__device__ float g_mtr2[OO];
__device__ float g_pA[SPLIT_A*BB*OO];
__device__ float g_pI[SPLIT_I*BB*OO];
__device__ int   g_nzcnt[NN];
__device__ int   g_nzcol[(size_t)NN*NN];
__device__ float g_nzval[(size_t)NN*NN];

__device__ __forceinline__ void split3(float w, bf16& h, bf16& m, bf16& l) {
    h = __float2bfloat16(w);
    float r1 = __fadd_rn(w, -__bfloat162float(h));
    m = __float2bfloat16(r1);
    float r2 = __fadd_rn(r1, -__bfloat162float(m));
    l = __float2bfloat16(r2);
}
__device__ __forceinline__ void split2(float w, bf16& h, bf16& l) {
    h = __float2bfloat16(w);
    l = __float2bfloat16(__fadd_rn(w, -__bfloat162float(h)));
}
__device__ __forceinline__ uint32_t s2u(const void* p) {
    return (uint32_t)__cvta_generic_to_shared(p);
}
__device__ __forceinline__ void cpa16(uint32_t d, const void* s) {
    asm volatile("cp.async.ca.shared.global [%0], [%1], 16;\n" :: "r"(d), "l"(s));
}
__device__ __forceinline__ void cpa_commit_wait() {
    asm volatile("cp.async.commit_group;\n");
    asm volatile("cp.async.wait_group 0;\n");
}
__device__ __forceinline__ uint32_t packbf2(bf16 a, bf16 b) {
    __nv_bfloat162 v(a, b);
    return *(uint32_t*)&v;
}

// ---------------- init ----------------
__global__ void k_init(const float* __restrict__ hw_in,
                       const float* __restrict__ eiw_in,
                       const float* __restrict__ iew_in) {
    int i = blockIdx.x * blockDim.x + threadIdx.x;
    if (i < OO*NN) {
        float w = hw_in[i];
        g_hw[i] = w;
        split3(w, g_hwh[i], g_hwm[i], g_hwl[i]);
    }
    if (i < BB*NN) {
        g_t1f[i] = 0.f;
        bf16 z = __float2bfloat16(0.f);
        g_t1h[i] = z; g_t1l[i] = z;
    }
    if (i < BB*DLY*OO) g_bufb[i] = __float2bfloat16(0.f);
    if (i < BB*OO) {
        g_v2[i]=0.f; g_vi[i]=0.f; g_tr2[i]=0.f; g_tri[i]=0.f;
        bf16 z = __float2bfloat16(0.f);
        g_tr2h[i]=z; g_tr2l[i]=z; g_trih[i]=z; g_tril[i]=z;
    }
    if (i < OO*OO) {
        int r = i / OO, c = i - r*OO;
        float w = (r == c) ? 0.f : iew_in[i];
        g_iew[i] = w;
        split3(w, g_iewh[i], g_iewm[i], g_iewl[i]);
    }
    if (i < OO) g_ediag[i] = eiw_in[i*OO + i];
}

// ---------------- CSR build ----------------
__global__ void k_csr(const float* __restrict__ W) {
    int wid  = (blockIdx.x * blockDim.x + threadIdx.x) >> 5;
    int lane = threadIdx.x & 31;
    if (wid >= NN) return;
    int cnt = 0;
    for (int base = 0; base < NN; base += 32) {
        float w = W[wid*NN + base + lane];
        unsigned m = __ballot_sync(0xffffffffu, w != 0.f);
        if (w != 0.f) {
            int pos = cnt + __popc(m & ((1u << lane) - 1u));
            g_nzcol[(size_t)wid*NN + pos] = base + lane;
            g_nzval[(size_t)wid*NN + pos] = w;
        }
        cnt += __popc(m);
    }
    if (lane == 0) g_nzcnt[wid] = cnt;
}

// ---------------- layer 1: all T steps, spikes -> fp32 out + bitmask ----------------
__global__ __launch_bounds__(256) void k_layer1_all(const float* __restrict__ x,
                                                    float* __restrict__ out_l1) {
    int idx = blockIdx.x * 256 + threadIdx.x;
    int b = idx >> 11;
    int n = idx & (NN - 1);
    int cnt = g_nzcnt[n];
    const int*   cp = g_nzcol + (size_t)n*NN;
    const float* vp = g_nzval + (size_t)n*NN;
    const float* xb = x + (size_t)b*TT*NN;
    float v = 0.f;
    for (int t = 0; t < TT; t++) {
        const float* xr = xb + (size_t)t*NN;
        float acc = 0.f;
        for (int j = 0; j < cnt; j++) acc = fmaf(xr[cp[j]], vp[j], acc);
        v = fmaf(ALPHA_F, v, acc);
        float s = (v > THRESH_F) ? 1.f : 0.f;
        v = (v > THRESH_F) ? 0.f : v;
        out_l1[((size_t)b*TT + t)*NN + n] = s;
        unsigned m = __ballot_sync(0xffffffffu, s > 0.f);
        if ((n & 31) == 0) g_spk[((size_t)t*BB + b)*64 + (n >> 5)] = m;
    }
}

extern __shared__ __align__(16) char smem_raw[];

// ---------------- gemm: m=128 x 64q tiles, one K-chunk of 128, 3 splits ----------------
// grid 160: chunk = bid >> 3 (0..19), qt = bid & 7. Blocks 0..127 also run tr1 tail.
__global__ __launch_bounds__(256) void k_gemm(int t, int tm) {
    bf16* sA = (bf16*)smem_raw;        // [128][136]
    bf16* sB = sA + 128*136;           // [3][64][136]
    int bid = blockIdx.x;
    int tid = threadIdx.x;
    int chunk = bid >> 3, qt = bid & 7;
    const bf16 *W0, *W1, *W2;
    int wstride, k0; float* part;
    uint32_t sAu = s2u(sA), sBu = s2u(sB);
    int q0 = qt*64;
    bool has_cpa = false;

    if (chunk < SPLIT_A) {
        k0 = chunk*128;
        W0 = g_hwh; W1 = g_hwm; W2 = g_hwl; wstride = NN;
        part = g_pA + (size_t)chunk*BB*OO;
        // decode spike bits -> bf16 tile [128][128]: thread handles 2 words of one row
        int r = tid >> 1, wsel = (tid & 1)*2;
        #pragma unroll
        for (int wd = 0; wd < 2; wd++) {
            uint32_t wbits = g_spk[((size_t)t*BB + r)*64 + (k0 >> 5) + wsel + wd];
            uint32_t* dst = (uint32_t*)(sA + r*136 + (wsel + wd)*32);
            #pragma unroll
            for (int i = 0; i < 16; i++) {
                uint32_t v = (((wbits >> (2*i)) & 1u) ? 0x3F80u : 0u)
                           | (((wbits >> (2*i+1)) & 1u) ? 0x3F800000u : 0u);
                dst[i] = v;
            }
        }
    } else {
        k0 = (chunk - SPLIT_A)*128;
        W0 = g_iewh; W1 = g_iewm; W2 = g_iewl; wstride = OO;
        part = g_pI + (size_t)(chunk - SPLIT_A)*BB*OO;
        const bf16* Asrc = g_bufb + tm*OO;
        #pragma unroll
        for (int i = 0; i < 8; i++) {
            int idx = tid + i*256;
            int r = idx >> 4, c8 = idx & 15;
            cpa16(sAu + (uint32_t)(r*136 + c8*8)*2u,
                  Asrc + (size_t)r*((size_t)DLY*OO) + k0 + c8*8);
        }
        has_cpa = true;
    }
    const bf16* Ws[3] = {W0, W1, W2};
    #pragma unroll
    for (int s = 0; s < 3; s++) {
        #pragma unroll
        for (int i = 0; i < 4; i++) {
            int idx = tid + i*256;
            int r = idx >> 4, c8 = idx & 15;
            cpa16(sBu + (uint32_t)((s*64 + r)*136 + c8*8)*2u,
                  Ws[s] + (size_t)(q0 + r)*wstride + k0 + c8*8);
        }
    }
    cpa_commit_wait();
    (void)has_cpa;
    __syncthreads();

    int w = tid >> 5, lane = tid & 31, g = lane >> 2, qi = lane & 3;
    int lr = lane & 7, lsel = lane >> 3;

    // hoist A fragments (8 k16, reused across 3 splits)
    uint32_t a[8][4];
    int arow = 16*w + lr + ((lsel & 1) ? 8 : 0);
    #pragma unroll
    for (int k16 = 0; k16 < 8; k16++) {
        int acol = k16*16 + ((lsel & 2) ? 8 : 0);
        uint32_t addr = sAu + (uint32_t)(arow*136 + acol)*2u;
        asm volatile("ldmatrix.sync.aligned.m8n8.x4.shared.b16 {%0,%1,%2,%3}, [%4];"
                     : "=r"(a[k16][0]), "=r"(a[k16][1]), "=r"(a[k16][2]), "=r"(a[k16][3])
                     : "r"(addr));
    }

    float acc[8][4];
    #pragma unroll
    for (int j = 0; j < 8; j++) { acc[j][0]=0.f; acc[j][1]=0.f; acc[j][2]=0.f; acc[j][3]=0.f; }

    int bcol_off = (lane & 8) ? 8 : 0;
    #pragma unroll
    for (int s = 0; s < 3; s++) {
        #pragma unroll
        for (int k16 = 0; k16 < 8; k16++) {
            #pragma unroll
            for (int j = 0; j < 8; j++) {
                uint32_t b0, b1;
                uint32_t baddr = sBu + (uint32_t)((s*64 + lr + j*8)*136 + k16*16 + bcol_off)*2u;
                asm volatile("ldmatrix.sync.aligned.m8n8.x2.shared.b16 {%0,%1}, [%2];"
                             : "=r"(b0), "=r"(b1) : "r"(baddr));
                asm volatile(
                    "mma.sync.aligned.m16n8k16.row.col.f32.bf16.bf16.f32 "
                    "{%0,%1,%2,%3},{%4,%5,%6,%7},{%8,%9},{%0,%1,%2,%3};\n"
                    : "+f"(acc[j][0]), "+f"(acc[j][1]), "+f"(acc[j][2]), "+f"(acc[j][3])
                    : "r"(a[k16][0]), "r"(a[k16][1]), "r"(a[k16][2]), "r"(a[k16][3]),
                      "r"(b0), "r"(b1));
            }
        }
    }
    int m0 = 16*w + g;
    #pragma unroll
    for (int j = 0; j < 8; j++) {
        int qc = q0 + j*8 + qi*2;
        *(float2*)(part + (size_t)m0*OO + qc)       = make_float2(acc[j][0], acc[j][1]);
        *(float2*)(part + (size_t)(m0 + 8)*OO + qc) = make_float2(acc[j][2], acc[j][3]);
    }

    // ---- tr1 rolling update tail: blocks 0..127, 2048 elements each ----
    if (bid < 128) {
        #pragma unroll
        for (int it = 0; it < 2; it++) {
            int base = bid*2048 + (tid + it*256)*4;
            int b = base >> 11, n = base & (NN - 1);
            uint32_t wbits = g_spk[((size_t)t*BB + b)*64 + (n >> 5)];
            int sh = n & 31;
            float4 tr = *(float4*)(g_t1f + base);
            float s0 = ((wbits >> (sh+0)) & 1u) ? 1.f : 0.f;
            float s1 = ((wbits >> (sh+1)) & 1u) ? 1.f : 0.f;
            float s2 = ((wbits >> (sh+2)) & 1u) ? 1.f : 0.f;
            float s3 = ((wbits >> (sh+3)) & 1u) ? 1.f : 0.f;
            tr.x = fmaf(DEC_F, tr.x, __fmul_rn(CDEC_F, s0));
            tr.y = fmaf(DEC_F, tr.y, __fmul_rn(CDEC_F, s1));
            tr.z = fmaf(DEC_F, tr.z, __fmul_rn(CDEC_F, s2));
            tr.w = fmaf(DEC_F, tr.w, __fmul_rn(CDEC_F, s3));
            *(float4*)(g_t1f + base) = tr;
            bf16 h0,l0,h1,l1,h2,l2,h3,l3;
            split2(tr.x, h0, l0); split2(tr.y, h1, l1);
            split2(tr.z, h2, l2); split2(tr.w, h3, l3);
            *(uint2*)(g_t1h + base) = make_uint2(packbf2(h0, h1), packbf2(h2, h3));
            *(uint2*)(g_t1l + base) = make_uint2(packbf2(l0, l1), packbf2(l2, l3));
        }
    }
}

// ---------------- epi: 64 blocks, R8-identical math ----------------
__global__ __launch_bounds__(256) void k_epi(float* __restrict__ out_l2, int t, int tm) {
    __shared__ float sh[3][32][8];
    int qb = blockIdx.x * 8;
    int tq = threadIdx.x & 7;
    int tb = threadIdx.x >> 3;
    int q  = qb + tq;

    float r2 = 0.f, ri = 0.f, rd = 0.f;
    for (int j = 0; j < 4; j++) {
        int b  = tb + 32*j;
        int bo = b*OO + q;
        float l1v = 0.f, io = 0.f;
        #pragma unroll
        for (int s = 0; s < SPLIT_A; s++) l1v = __fadd_rn(l1v, g_pA[(size_t)s*BB*OO + bo]);
        #pragma unroll
        for (int s = 0; s < SPLIT_I; s++) io  = __fadd_rn(io,  g_pI[(size_t)s*BB*OO + bo]);
        float v = fmaf(ALPHA_F, g_v2[bo], __fadd_rn(l1v, -io));
        float s2 = (v > THRESH_F) ? 1.f : 0.f;
        g_v2[bo] = (v > THRESH_F) ? 0.f : v;
        out_l2[((size_t)b*TT + t)*OO + q] = s2;
        float t2 = fmaf(DEC_F, g_tr2[bo], __fmul_rn(CDEC_F, s2));
        g_tr2[bo] = t2;
        { bf16 h, l; split2(t2, h, l); g_tr2h[bo] = h; g_tr2l[bo] = l; }
        float inh_in = __fmul_rn(s2, g_ediag[q]);
        float vv = fmaf(ALPHA_F, g_vi[bo], inh_in);
        float si = (vv > THRESH_F) ? 1.f : 0.f;
        g_vi[bo] = (vv > THRESH_F) ? 0.f : vv;
        g_bufb[((size_t)b*DLY + tm)*OO + q] = __float2bfloat16(si);
        float ti = fmaf(DEC_F, g_tri[bo], __fmul_rn(CDEC_F, si));
        g_tri[bo] = ti;
        { bf16 h, l; split2(ti, h, l); g_trih[bo] = h; g_tril[bo] = l; }
        r2 += t2; ri += ti; rd = fmaf(ti, t2, rd);
    }
    sh[0][tb][tq] = r2; sh[1][tb][tq] = ri; sh[2][tb][tq] = rd;
    __syncthreads();
    if (tb == 0) {
        float s2 = 0.f, si = 0.f, sd = 0.f;
        for (int g = 0; g < 32; g++) { s2 += sh[0][g][tq]; si += sh[1][g][tq]; sd += sh[2][g][tq]; }
        float m2 = s2 * INVB_F, mi = si * INVB_F;
        g_mtr2[q] = m2;
        float e = g_ediag[q];
        float dw = fmaf(A_PLUS_F, __fmul_rn(sd, INVB_F),
                        -__fmul_rn(__fmul_rn(A_MINUS_F, e), mi));
        g_ediag[q] = __fadd_rn(e, dw);
    }
}

// ---------------- plast: 64q x 128p tiles (R9-validated), grid 160 ----------------
// item 0..159: 0..127 hw (px=item&15, qy=item>>4); 128..159 iew (px=i2&3, qy=i2>>2)
__global__ __launch_bounds__(256) void k_plast(int t) {
    bf16* sAh = (bf16*)smem_raw;        // [b=128][72]  (tr2 hi)
    bf16* sAl = sAh + 128*72;
    bf16* sB0 = sAl + 128*72;           // [b=128][136] (pre hi, 128 p cols)
    bf16* sB1 = sB0 + 128*136;
    int item = blockIdx.x;
    int mode, p0, q0;
    if (item < 128) { mode = 0; p0 = (item & 15) * 128; q0 = (item >> 4) * 64; }
    else { int i2 = item - 128; mode = 1; p0 = (i2 & 3) * 128; q0 = (i2 >> 2) * 64; }
    const bf16* preh = mode ? g_trih : g_t1h;
    const bf16* prel = mode ? g_tril : g_t1l;
    int P = mode ? OO : NN;
    float* W = mode ? g_iew : g_hw;
    bf16 *Wh = mode ? g_iewh : g_hwh, *Wm = mode ? g_iewm : g_hwm, *Wl = mode ? g_iewl : g_hwl;

    int tid = threadIdx.x;
    uint32_t sAhu = s2u(sAh), sAlu = s2u(sAl), sB0u = s2u(sB0), sB1u = s2u(sB1);

    #pragma unroll
    for (int i = 0; i < 4; i++) {
        int idx = tid + i*256;
        int b = idx >> 3, c8 = idx & 7;
        uint32_t so = (uint32_t)(b*72 + c8*8)*2u;
        cpa16(sAhu + so, g_tr2h + b*OO + q0 + c8*8);
        cpa16(sAlu + so, g_tr2l + b*OO + q0 + c8*8);
    }
    #pragma unroll
    for (int i = 0; i < 8; i++) {
        int idx = tid + i*256;
        int b = idx >> 4, c8 = idx & 15;
        uint32_t so = (uint32_t)(b*136 + c8*8)*2u;
        cpa16(sB0u + so, preh + (size_t)b*P + p0 + c8*8);
        cpa16(sB1u + so, prel + (size_t)b*P + p0 + c8*8);
    }
    cpa_commit_wait();
    __syncthreads();

    int w = tid >> 5, lane = tid & 31, g = lane >> 2, qi = lane & 3;
    int r8 = lane & 7, sel = lane >> 3;

    float acc[4][2][4];
    #pragma unroll
    for (int mi = 0; mi < 4; mi++)
        #pragma unroll
        for (int st = 0; st < 2; st++)
            { acc[mi][st][0]=0.f; acc[mi][st][1]=0.f; acc[mi][st][2]=0.f; acc[mi][st][3]=0.f; }

    #pragma unroll
    for (int k16 = 0; k16 < 8; k16++) {
        int kb16 = k16*16;
        int rrB = kb16 + ((sel & 1) ? 8 : 0) + r8;
        uint32_t bh[2][2], bl[2][2];
        #pragma unroll
        for (int st = 0; st < 2; st++) {
            uint32_t bo = (uint32_t)(rrB*136 + w*16 + st*8)*2u;
            asm volatile("ldmatrix.sync.aligned.m8n8.x2.trans.shared.b16 {%0,%1}, [%2];"
                         : "=r"(bh[st][0]), "=r"(bh[st][1]) : "r"(sB0u + bo));
            asm volatile("ldmatrix.sync.aligned.m8n8.x2.trans.shared.b16 {%0,%1}, [%2];"
                         : "=r"(bl[st][0]), "=r"(bl[st][1]) : "r"(sB1u + bo));
        }
        int rrA = kb16 + ((sel & 2) ? 8 : 0) + r8;
        #pragma unroll
        for (int mi = 0; mi < 4; mi++) {
            int cc = mi*16 + ((sel & 1) ? 8 : 0);
            uint32_t ao = (uint32_t)(rrA*72 + cc)*2u;
            #pragma unroll
            for (int as = 0; as < 2; as++) {
                uint32_t a0, a1, a2, a3;
                asm volatile("ldmatrix.sync.aligned.m8n8.x4.trans.shared.b16 {%0,%1,%2,%3}, [%4];"
                             : "=r"(a0), "=r"(a1), "=r"(a2), "=r"(a3)
                             : "r"((as ? sAlu : sAhu) + ao));
                #pragma unroll
                for (int st = 0; st < 2; st++) {
                    asm volatile(
                        "mma.sync.aligned.m16n8k16.row.col.f32.bf16.bf16.f32 "
                        "{%0,%1,%2,%3},{%4,%5,%6,%7},{%8,%9},{%0,%1,%2,%3};\n"
                        : "+f"(acc[mi][st][0]), "+f"(acc[mi][st][1]),
                          "+f"(acc[mi][st][2]), "+f"(acc[mi][st][3])
                        : "r"(a0), "r"(a1), "r"(a2), "r"(a3), "r"(bh[st][0]), "r"(bh[st][1]));
                    asm volatile(
                        "mma.sync.aligned.m16n8k16.row.col.f32.bf16.bf16.f32 "
                        "{%0,%1,%2,%3},{%4,%5,%6,%7},{%8,%9},{%0,%1,%2,%3};\n"
                        : "+f"(acc[mi][st][0]), "+f"(acc[mi][st][1]),
                          "+f"(acc[mi][st][2]), "+f"(acc[mi][st][3])
                        : "r"(a0), "r"(a1), "r"(a2), "r"(a3), "r"(bl[st][0]), "r"(bl[st][1]));
                }
            }
        }
    }

    #pragma unroll
    for (int mi = 0; mi < 4; mi++) {
        #pragma unroll
        for (int st = 0; st < 2; st++) {
            int pc = p0 + w*16 + st*8 + qi*2;
            #pragma unroll
            for (int half = 0; half < 2; half++) {
                int qq = q0 + mi*16 + g + half*8;
                float h0 = acc[mi][st][half*2 + 0], h1 = acc[mi][st][half*2 + 1];
                float mean = g_mtr2[qq];
                size_t wbase = (size_t)qq*P + pc;
                float2 wv = *(float2*)(W + wbase);
                float dw0 = fmaf(A_PLUS_F, __fmul_rn(h0, INVB_F),
                                 -__fmul_rn(__fmul_rn(A_MINUS_F, wv.x), mean));
                float dw1 = fmaf(A_PLUS_F, __fmul_rn(h1, INVB_F),
                                 -__fmul_rn(__fmul_rn(A_MINUS_F, wv.y), mean));
                float nw0 = __fadd_rn(wv.x, dw0);
                float nw1 = __fadd_rn(wv.y, dw1);
                if (mode && qq == pc)     nw0 = 0.f;
                if (mode && qq == pc + 1) nw1 = 0.f;
                *(float2*)(W + wbase) = make_float2(nw0, nw1);
                bf16 h, m, l, h2, m2, l2;
                split3(nw0, h, m, l);
                split3(nw1, h2, m2, l2);
                *(__nv_bfloat162*)(Wh + wbase) = __nv_bfloat162(h, h2);
                *(__nv_bfloat162*)(Wm + wbase) = __nv_bfloat162(m, m2);
                *(__nv_bfloat162*)(Wl + wbase) = __nv_bfloat162(l, l2);
            }
        }
    }
}

// ---------------- launch ----------------
extern "C" void kernel_launch(void* const* d_in, const int* in_sizes, int n_in,
                              void* d_out, int out_size) {
    const float* x      = (const float*)d_in[0];
    const float* win    = (const float*)d_in[1];
    const float* hw_in  = (const float*)d_in[2];
    const float* eiw_in = (const float*)d_in[3];
    const float* iew_in = (const float*)d_in[4];
    float* out_l1 = (float*)d_out;
    float* out_l2 = out_l1 + (size_t)BB*TT*NN;

    const int sm_gemm  = (128*136 + 3*64*136) * 2;   // 87040
    const int sm_plast = (2*128*72 + 2*128*136) * 2; // 106496
    cudaFuncSetAttribute(k_gemm,  cudaFuncAttributeMaxDynamicSharedMemorySize, sm_gemm);
    cudaFuncSetAttribute(k_plast, cudaFuncAttributeMaxDynamicSharedMemorySize, sm_plast);

    k_init<<<(OO*NN)/256, 256>>>(hw_in, eiw_in, iew_in);
    k_csr<<<256, 256>>>(win);
    k_layer1_all<<<(BB*NN)/256, 256>>>(x, out_l1);

    for (int t = 0; t < TT; t++) {
        int tm = t % DLY;
        k_gemm<<<160, 256, sm_gemm>>>(t, tm);
        k_epi<<<64, 256>>>(out_l2, t, tm);
        k_plast<<<160, 256, sm_plast>>>(t);
    }
}

// round 15
// speedup vs baseline: 1.0550x; 1.0234x over previous
#include <cuda_runtime.h>
#include <cuda_bf16.h>
#include <cstdint>

#define BB 128
#define TT 100
#define NN 2048
#define OO 512
#define DLY 10

#define ALPHA_F   0.90483741803595957316f   // exp(-1/10)
#define DEC_F     0.95122942450071400910f   // exp(-1/20)
#define CDEC_F    0.04877057549928599090f   // 1 - exp(-1/20)
#define THRESH_F  0.02f
#define A_PLUS_F  1e-4f
#define A_MINUS_F 1e-4f
#define INVB_F    0.0078125f                // 1/128, exact

#define SPLIT_A 16
#define SPLIT_I 4

typedef __nv_bfloat16 bf16;

// ---------------- state ----------------
__device__ uint32_t g_spk[(size_t)TT*BB*64];        // l1 spikes as bits (3.2MB)
__device__ float g_t1f[BB*NN];                      // rolling tr1 fp32
__device__ bf16  g_t1h[BB*NN], g_t1l[BB*NN];        // rolling tr1 splits
__device__ float g_v2 [BB*OO];
__device__ float g_vi [BB*OO];
__device__ float g_tr2[BB*OO];
__device__ float g_tri[BB*OO];
__device__ bf16  g_tr2h[BB*OO], g_tr2l[BB*OO];
__device__ bf16  g_trih[BB*OO], g_tril[BB*OO];
__device__ bf16  g_bufb[BB*DLY*OO];
__device__ float g_hw [(size_t)OO*NN];
__device__ float g_iew[OO*OO];
__device__ float g_ediag[OO];
__device__ float g_mtr2[OO];
__device__ float g_pA[SPLIT_A*BB*OO];
__device__ float g_pI[SPLIT_I*BB*OO];
__device__ int   g_nzcnt[NN];
__device__ int   g_nzcol[(size_t)NN*NN];
__device__ float g_nzval[(size_t)NN*NN];

__device__ __forceinline__ void split3(float w, bf16& h, bf16& m, bf16& l) {
    h = __float2bfloat16(w);
    float r1 = __fadd_rn(w, -__bfloat162float(h));
    m = __float2bfloat16(r1);
    float r2 = __fadd_rn(r1, -__bfloat162float(m));
    l = __float2bfloat16(r2);
}
__device__ __forceinline__ void split2(float w, bf16& h, bf16& l) {
    h = __float2bfloat16(w);
    l = __float2bfloat16(__fadd_rn(w, -__bfloat162float(h)));
}
__device__ __forceinline__ uint32_t s2u(const void* p) {
    return (uint32_t)__cvta_generic_to_shared(p);
}
__device__ __forceinline__ void cpa16(uint32_t d, const void* s) {
    asm volatile("cp.async.ca.shared.global [%0], [%1], 16;\n" :: "r"(d), "l"(s));
}
__device__ __forceinline__ void cpa_commit_wait() {
    asm volatile("cp.async.commit_group;\n");
    asm volatile("cp.async.wait_group 0;\n");
}
__device__ __forceinline__ uint32_t packbf2(bf16 a, bf16 b) {
    __nv_bfloat162 v(a, b);
    return *(uint32_t*)&v;
}

// ---------------- init ----------------
__global__ void k_init(const float* __restrict__ hw_in,
                       const float* __restrict__ eiw_in,
                       const float* __restrict__ iew_in) {
    int i = blockIdx.x * blockDim.x + threadIdx.x;
    if (i < OO*NN) g_hw[i] = hw_in[i];
    if (i < BB*NN) {
        g_t1f[i] = 0.f;
        bf16 z = __float2bfloat16(0.f);
        g_t1h[i] = z; g_t1l[i] = z;
    }
    if (i < BB*DLY*OO) g_bufb[i] = __float2bfloat16(0.f);
    if (i < BB*OO) {
        g_v2[i]=0.f; g_vi[i]=0.f; g_tr2[i]=0.f; g_tri[i]=0.f;
        bf16 z = __float2bfloat16(0.f);
        g_tr2h[i]=z; g_tr2l[i]=z; g_trih[i]=z; g_tril[i]=z;
    }
    if (i < OO*OO) {
        int r = i / OO, c = i - r*OO;
        g_iew[i] = (r == c) ? 0.f : iew_in[i];
    }
    if (i < OO) g_ediag[i] = eiw_in[i*OO + i];
}

// ---------------- CSR build ----------------
__global__ void k_csr(const float* __restrict__ W) {
    int wid  = (blockIdx.x * blockDim.x + threadIdx.x) >> 5;
    int lane = threadIdx.x & 31;
    if (wid >= NN) return;
    int cnt = 0;
    for (int base = 0; base < NN; base += 32) {
        float w = W[wid*NN + base + lane];
        unsigned m = __ballot_sync(0xffffffffu, w != 0.f);
        if (w != 0.f) {
            int pos = cnt + __popc(m & ((1u << lane) - 1u));
            g_nzcol[(size_t)wid*NN + pos] = base + lane;
            g_nzval[(size_t)wid*NN + pos] = w;
        }
        cnt += __popc(m);
    }
    if (lane == 0) g_nzcnt[wid] = cnt;
}

// ---------------- layer 1: all T steps, spikes -> fp32 out + bitmask ----------------
__global__ __launch_bounds__(256) void k_layer1_all(const float* __restrict__ x,
                                                    float* __restrict__ out_l1) {
    int idx = blockIdx.x * 256 + threadIdx.x;
    int b = idx >> 11;
    int n = idx & (NN - 1);
    int cnt = g_nzcnt[n];
    const int*   cp = g_nzcol + (size_t)n*NN;
    const float* vp = g_nzval + (size_t)n*NN;
    const float* xb = x + (size_t)b*TT*NN;
    float v = 0.f;
    for (int t = 0; t < TT; t++) {
        const float* xr = xb + (size_t)t*NN;
        float acc = 0.f;
        for (int j = 0; j < cnt; j++) acc = fmaf(xr[cp[j]], vp[j], acc);
        v = fmaf(ALPHA_F, v, acc);
        float s = (v > THRESH_F) ? 1.f : 0.f;
        v = (v > THRESH_F) ? 0.f : v;
        out_l1[((size_t)b*TT + t)*NN + n] = s;
        unsigned m = __ballot_sync(0xffffffffu, s > 0.f);
        if ((n & 31) == 0) g_spk[((size_t)t*BB + b)*64 + (n >> 5)] = m;
    }
}

extern __shared__ __align__(16) char smem_raw[];

// ---------------- gemm: m=128 x 64q tiles; W fp32 loaded + split in-register ----------------
// grid 160: chunk = bid >> 3 (0..19), qt = bid & 7. Blocks 0..127 also run tr1 tail.
__global__ __launch_bounds__(256) void k_gemm(int t, int tm) {
    bf16* sA = (bf16*)smem_raw;        // [128][136]
    bf16* sB = sA + 128*136;           // [3][64][136]
    int bid = blockIdx.x;
    int tid = threadIdx.x;
    int chunk = bid >> 3, qt = bid & 7;
    const float* Wf;
    int wstride, k0; float* part;
    uint32_t sAu = s2u(sA), sBu = s2u(sB);
    int q0 = qt*64;
    bool iew_path = (chunk >= SPLIT_A);

    if (!iew_path) {
        k0 = chunk*128;
        Wf = g_hw; wstride = NN;
        part = g_pA + (size_t)chunk*BB*OO;
        // decode spike bits -> bf16 tile [128][128]
        int r = tid >> 1, wsel = (tid & 1)*2;
        #pragma unroll
        for (int wd = 0; wd < 2; wd++) {
            uint32_t wbits = g_spk[((size_t)t*BB + r)*64 + (k0 >> 5) + wsel + wd];
            uint32_t* dst = (uint32_t*)(sA + r*136 + (wsel + wd)*32);
            #pragma unroll
            for (int i = 0; i < 16; i++) {
                uint32_t v = (((wbits >> (2*i)) & 1u) ? 0x3F80u : 0u)
                           | (((wbits >> (2*i+1)) & 1u) ? 0x3F800000u : 0u);
                dst[i] = v;
            }
        }
    } else {
        k0 = (chunk - SPLIT_A)*128;
        Wf = g_iew; wstride = OO;
        part = g_pI + (size_t)(chunk - SPLIT_A)*BB*OO;
        const bf16* Asrc = g_bufb + tm*OO;
        #pragma unroll
        for (int i = 0; i < 8; i++) {
            int idx = tid + i*256;
            int r = idx >> 4, c8 = idx & 15;
            cpa16(sAu + (uint32_t)(r*136 + c8*8)*2u,
                  Asrc + (size_t)r*((size_t)DLY*OO) + k0 + c8*8);
        }
        cpa_commit_wait();
    }

    // weight fp32 load + in-register 3-way split -> sB[3] tiles (each element split once)
    {
        int r = tid >> 2, cb = (tid & 3) * 32;
        const float* wrow = Wf + (size_t)(q0 + r)*wstride + k0 + cb;
        bf16* sh_ = sB + r*136 + cb;
        bf16* sm_ = sB + (64 + r)*136 + cb;
        bf16* sl_ = sB + (128 + r)*136 + cb;
        #pragma unroll
        for (int i = 0; i < 8; i++) {
            float4 wv = *(const float4*)(wrow + i*4);
            bf16 h0,m0,l0,h1,m1,l1,h2,m2,l2,h3,m3,l3;
            split3(wv.x, h0, m0, l0);
            split3(wv.y, h1, m1, l1);
            split3(wv.z, h2, m2, l2);
            split3(wv.w, h3, m3, l3);
            *(uint2*)(sh_ + i*4) = make_uint2(packbf2(h0, h1), packbf2(h2, h3));
            *(uint2*)(sm_ + i*4) = make_uint2(packbf2(m0, m1), packbf2(m2, m3));
            *(uint2*)(sl_ + i*4) = make_uint2(packbf2(l0, l1), packbf2(l2, l3));
        }
    }
    __syncthreads();

    int w = tid >> 5, lane = tid & 31, g = lane >> 2, qi = lane & 3;
    int lr = lane & 7, lsel = lane >> 3;

    float acc[8][4];
    #pragma unroll
    for (int j = 0; j < 8; j++) { acc[j][0]=0.f; acc[j][1]=0.f; acc[j][2]=0.f; acc[j][3]=0.f; }

    int arow = 16*w + lr + ((lsel & 1) ? 8 : 0);
    int bcol_off = (lane & 8) ? 8 : 0;
    // s-major, k16, j: accumulation order identical to R14
    #pragma unroll
    for (int s = 0; s < 3; s++) {
        #pragma unroll
        for (int k16 = 0; k16 < 8; k16++) {
            uint32_t a0, a1, a2, a3;
            int acol = k16*16 + ((lsel & 2) ? 8 : 0);
            asm volatile("ldmatrix.sync.aligned.m8n8.x4.shared.b16 {%0,%1,%2,%3}, [%4];"
                         : "=r"(a0), "=r"(a1), "=r"(a2), "=r"(a3)
                         : "r"(sAu + (uint32_t)(arow*136 + acol)*2u));
            #pragma unroll
            for (int j = 0; j < 8; j++) {
                uint32_t b0, b1;
                uint32_t baddr = sBu + (uint32_t)((s*64 + lr + j*8)*136 + k16*16 + bcol_off)*2u;
                asm volatile("ldmatrix.sync.aligned.m8n8.x2.shared.b16 {%0,%1}, [%2];"
                             : "=r"(b0), "=r"(b1) : "r"(baddr));
                asm volatile(
                    "mma.sync.aligned.m16n8k16.row.col.f32.bf16.bf16.f32 "
                    "{%0,%1,%2,%3},{%4,%5,%6,%7},{%8,%9},{%0,%1,%2,%3};\n"
                    : "+f"(acc[j][0]), "+f"(acc[j][1]), "+f"(acc[j][2]), "+f"(acc[j][3])
                    : "r"(a0), "r"(a1), "r"(a2), "r"(a3), "r"(b0), "r"(b1));
            }
        }
    }
    int m0 = 16*w + g;
    #pragma unroll
    for (int j = 0; j < 8; j++) {
        int qc = q0 + j*8 + qi*2;
        *(float2*)(part + (size_t)m0*OO + qc)       = make_float2(acc[j][0], acc[j][1]);
        *(float2*)(part + (size_t)(m0 + 8)*OO + qc) = make_float2(acc[j][2], acc[j][3]);
    }

    // ---- tr1 rolling update tail: blocks 0..127, 2048 elements each ----
    if (bid < 128) {
        #pragma unroll
        for (int it = 0; it < 2; it++) {
            int base = bid*2048 + (tid + it*256)*4;
            int b = base >> 11, n = base & (NN - 1);
            uint32_t wbits = g_spk[((size_t)t*BB + b)*64 + (n >> 5)];
            int sh = n & 31;
            float4 tr = *(float4*)(g_t1f + base);
            float s0 = ((wbits >> (sh+0)) & 1u) ? 1.f : 0.f;
            float s1 = ((wbits >> (sh+1)) & 1u) ? 1.f : 0.f;
            float s2 = ((wbits >> (sh+2)) & 1u) ? 1.f : 0.f;
            float s3 = ((wbits >> (sh+3)) & 1u) ? 1.f : 0.f;
            tr.x = fmaf(DEC_F, tr.x, __fmul_rn(CDEC_F, s0));
            tr.y = fmaf(DEC_F, tr.y, __fmul_rn(CDEC_F, s1));
            tr.z = fmaf(DEC_F, tr.z, __fmul_rn(CDEC_F, s2));
            tr.w = fmaf(DEC_F, tr.w, __fmul_rn(CDEC_F, s3));
            *(float4*)(g_t1f + base) = tr;
            bf16 h0,l0,h1,l1,h2,l2,h3,l3;
            split2(tr.x, h0, l0); split2(tr.y, h1, l1);
            split2(tr.z, h2, l2); split2(tr.w, h3, l3);
            *(uint2*)(g_t1h + base) = make_uint2(packbf2(h0, h1), packbf2(h2, h3));
            *(uint2*)(g_t1l + base) = make_uint2(packbf2(l0, l1), packbf2(l2, l3));
        }
    }
}

// ---------------- epi: 64 blocks, R8-identical math ----------------
__global__ __launch_bounds__(256) void k_epi(float* __restrict__ out_l2, int t, int tm) {
    __shared__ float sh[3][32][8];
    int qb = blockIdx.x * 8;
    int tq = threadIdx.x & 7;
    int tb = threadIdx.x >> 3;
    int q  = qb + tq;

    float r2 = 0.f, ri = 0.f, rd = 0.f;
    for (int j = 0; j < 4; j++) {
        int b  = tb + 32*j;
        int bo = b*OO + q;
        float l1v = 0.f, io = 0.f;
        #pragma unroll
        for (int s = 0; s < SPLIT_A; s++) l1v = __fadd_rn(l1v, g_pA[(size_t)s*BB*OO + bo]);
        #pragma unroll
        for (int s = 0; s < SPLIT_I; s++) io  = __fadd_rn(io,  g_pI[(size_t)s*BB*OO + bo]);
        float v = fmaf(ALPHA_F, g_v2[bo], __fadd_rn(l1v, -io));
        float s2 = (v > THRESH_F) ? 1.f : 0.f;
        g_v2[bo] = (v > THRESH_F) ? 0.f : v;
        out_l2[((size_t)b*TT + t)*OO + q] = s2;
        float t2 = fmaf(DEC_F, g_tr2[bo], __fmul_rn(CDEC_F, s2));
        g_tr2[bo] = t2;
        { bf16 h, l; split2(t2, h, l); g_tr2h[bo] = h; g_tr2l[bo] = l; }
        float inh_in = __fmul_rn(s2, g_ediag[q]);
        float vv = fmaf(ALPHA_F, g_vi[bo], inh_in);
        float si = (vv > THRESH_F) ? 1.f : 0.f;
        g_vi[bo] = (vv > THRESH_F) ? 0.f : vv;
        g_bufb[((size_t)b*DLY + tm)*OO + q] = __float2bfloat16(si);
        float ti = fmaf(DEC_F, g_tri[bo], __fmul_rn(CDEC_F, si));
        g_tri[bo] = ti;
        { bf16 h, l; split2(ti, h, l); g_trih[bo] = h; g_tril[bo] = l; }
        r2 += t2; ri += ti; rd = fmaf(ti, t2, rd);
    }
    sh[0][tb][tq] = r2; sh[1][tb][tq] = ri; sh[2][tb][tq] = rd;
    __syncthreads();
    if (tb == 0) {
        float s2 = 0.f, si = 0.f, sd = 0.f;
        for (int g = 0; g < 32; g++) { s2 += sh[0][g][tq]; si += sh[1][g][tq]; sd += sh[2][g][tq]; }
        float m2 = s2 * INVB_F, mi = si * INVB_F;
        g_mtr2[q] = m2;
        float e = g_ediag[q];
        float dw = fmaf(A_PLUS_F, __fmul_rn(sd, INVB_F),
                        -__fmul_rn(__fmul_rn(A_MINUS_F, e), mi));
        g_ediag[q] = __fadd_rn(e, dw);
    }
}

// ---------------- plast: 64q x 128p tiles, fp32 weight RMW only ----------------
// item 0..159: 0..127 hw (px=item&15, qy=item>>4); 128..159 iew (px=i2&3, qy=i2>>2)
__global__ __launch_bounds__(256) void k_plast(int t) {
    bf16* sAh = (bf16*)smem_raw;        // [b=128][72]  (tr2 hi)
    bf16* sAl = sAh + 128*72;
    bf16* sB0 = sAl + 128*72;           // [b=128][136] (pre hi, 128 p cols)
    bf16* sB1 = sB0 + 128*136;
    int item = blockIdx.x;
    int mode, p0, q0;
    if (item < 128) { mode = 0; p0 = (item & 15) * 128; q0 = (item >> 4) * 64; }
    else { int i2 = item - 128; mode = 1; p0 = (i2 & 3) * 128; q0 = (i2 >> 2) * 64; }
    const bf16* preh = mode ? g_trih : g_t1h;
    const bf16* prel = mode ? g_tril : g_t1l;
    int P = mode ? OO : NN;
    float* W = mode ? g_iew : g_hw;

    int tid = threadIdx.x;
    uint32_t sAhu = s2u(sAh), sAlu = s2u(sAl), sB0u = s2u(sB0), sB1u = s2u(sB1);

    #pragma unroll
    for (int i = 0; i < 4; i++) {
        int idx = tid + i*256;
        int b = idx >> 3, c8 = idx & 7;
        uint32_t so = (uint32_t)(b*72 + c8*8)*2u;
        cpa16(sAhu + so, g_tr2h + b*OO + q0 + c8*8);
        cpa16(sAlu + so, g_tr2l + b*OO + q0 + c8*8);
    }
    #pragma unroll
    for (int i = 0; i < 8; i++) {
        int idx = tid + i*256;
        int b = idx >> 4, c8 = idx & 15;
        uint32_t so = (uint32_t)(b*136 + c8*8)*2u;
        cpa16(sB0u + so, preh + (size_t)b*P + p0 + c8*8);
        cpa16(sB1u + so, prel + (size_t)b*P + p0 + c8*8);
    }
    cpa_commit_wait();
    __syncthreads();

    int w = tid >> 5, lane = tid & 31, g = lane >> 2, qi = lane & 3;
    int r8 = lane & 7, sel = lane >> 3;

    float acc[4][2][4];
    #pragma unroll
    for (int mi = 0; mi < 4; mi++)
        #pragma unroll
        for (int st = 0; st < 2; st++)
            { acc[mi][st][0]=0.f; acc[mi][st][1]=0.f; acc[mi][st][2]=0.f; acc[mi][st][3]=0.f; }

    #pragma unroll
    for (int k16 = 0; k16 < 8; k16++) {
        int kb16 = k16*16;
        int rrB = kb16 + ((sel & 1) ? 8 : 0) + r8;
        uint32_t bh[2][2], bl[2][2];
        #pragma unroll
        for (int st = 0; st < 2; st++) {
            uint32_t bo = (uint32_t)(rrB*136 + w*16 + st*8)*2u;
            asm volatile("ldmatrix.sync.aligned.m8n8.x2.trans.shared.b16 {%0,%1}, [%2];"
                         : "=r"(bh[st][0]), "=r"(bh[st][1]) : "r"(sB0u + bo));
            asm volatile("ldmatrix.sync.aligned.m8n8.x2.trans.shared.b16 {%0,%1}, [%2];"
                         : "=r"(bl[st][0]), "=r"(bl[st][1]) : "r"(sB1u + bo));
        }
        int rrA = kb16 + ((sel & 2) ? 8 : 0) + r8;
        #pragma unroll
        for (int mi = 0; mi < 4; mi++) {
            int cc = mi*16 + ((sel & 1) ? 8 : 0);
            uint32_t ao = (uint32_t)(rrA*72 + cc)*2u;
            #pragma unroll
            for (int as = 0; as < 2; as++) {
                uint32_t a0, a1, a2, a3;
                asm volatile("ldmatrix.sync.aligned.m8n8.x4.trans.shared.b16 {%0,%1,%2,%3}, [%4];"
                             : "=r"(a0), "=r"(a1), "=r"(a2), "=r"(a3)
                             : "r"((as ? sAlu : sAhu) + ao));
                #pragma unroll
                for (int st = 0; st < 2; st++) {
                    asm volatile(
                        "mma.sync.aligned.m16n8k16.row.col.f32.bf16.bf16.f32 "
                        "{%0,%1,%2,%3},{%4,%5,%6,%7},{%8,%9},{%0,%1,%2,%3};\n"
                        : "+f"(acc[mi][st][0]), "+f"(acc[mi][st][1]),
                          "+f"(acc[mi][st][2]), "+f"(acc[mi][st][3])
                        : "r"(a0), "r"(a1), "r"(a2), "r"(a3), "r"(bh[st][0]), "r"(bh[st][1]));
                    asm volatile(
                        "mma.sync.aligned.m16n8k16.row.col.f32.bf16.bf16.f32 "
                        "{%0,%1,%2,%3},{%4,%5,%6,%7},{%8,%9},{%0,%1,%2,%3};\n"
                        : "+f"(acc[mi][st][0]), "+f"(acc[mi][st][1]),
                          "+f"(acc[mi][st][2]), "+f"(acc[mi][st][3])
                        : "r"(a0), "r"(a1), "r"(a2), "r"(a3), "r"(bl[st][0]), "r"(bl[st][1]));
                }
            }
        }
    }

    #pragma unroll
    for (int mi = 0; mi < 4; mi++) {
        #pragma unroll
        for (int st = 0; st < 2; st++) {
            int pc = p0 + w*16 + st*8 + qi*2;
            #pragma unroll
            for (int half = 0; half < 2; half++) {
                int qq = q0 + mi*16 + g + half*8;
                float h0 = acc[mi][st][half*2 + 0], h1 = acc[mi][st][half*2 + 1];
                float mean = g_mtr2[qq];
                size_t wbase = (size_t)qq*P + pc;
                float2 wv = *(float2*)(W + wbase);
                float dw0 = fmaf(A_PLUS_F, __fmul_rn(h0, INVB_F),
                                 -__fmul_rn(__fmul_rn(A_MINUS_F, wv.x), mean));
                float dw1 = fmaf(A_PLUS_F, __fmul_rn(h1, INVB_F),
                                 -__fmul_rn(__fmul_rn(A_MINUS_F, wv.y), mean));
                float nw0 = __fadd_rn(wv.x, dw0);
                float nw1 = __fadd_rn(wv.y, dw1);
                if (mode && qq == pc)     nw0 = 0.f;
                if (mode && qq == pc + 1) nw1 = 0.f;
                *(float2*)(W + wbase) = make_float2(nw0, nw1);
            }
        }
    }
}

// ---------------- launch ----------------
extern "C" void kernel_launch(void* const* d_in, const int* in_sizes, int n_in,
                              void* d_out, int out_size) {
    const float* x      = (const float*)d_in[0];
    const float* win    = (const float*)d_in[1];
    const float* hw_in  = (const float*)d_in[2];
    const float* eiw_in = (const float*)d_in[3];
    const float* iew_in = (const float*)d_in[4];
    float* out_l1 = (float*)d_out;
    float* out_l2 = out_l1 + (size_t)BB*TT*NN;

    const int sm_gemm  = (128*136 + 3*64*136) * 2;   // 87040
    const int sm_plast = (2*128*72 + 2*128*136) * 2; // 106496
    cudaFuncSetAttribute(k_gemm,  cudaFuncAttributeMaxDynamicSharedMemorySize, sm_gemm);
    cudaFuncSetAttribute(k_plast, cudaFuncAttributeMaxDynamicSharedMemorySize, sm_plast);

    k_init<<<(OO*NN)/256, 256>>>(hw_in, eiw_in, iew_in);
    k_csr<<<256, 256>>>(win);
    k_layer1_all<<<(BB*NN)/256, 256>>>(x, out_l1);

    for (int t = 0; t < TT; t++) {
        int tm = t % DLY;
        k_gemm<<<160, 256, sm_gemm>>>(t, tm);
        k_epi<<<64, 256>>>(out_l2, t, tm);
        k_plast<<<160, 256, sm_plast>>>(t);
    }
}

// round 16
// speedup vs baseline: 1.0728x; 1.0169x over previous
#include <cuda_runtime.h>
#include <cuda_bf16.h>
#include <cstdint>

#define BB 128
#define TT 100
#define NN 2048
#define OO 512
#define DLY 10

#define ALPHA_F   0.90483741803595957316f   // exp(-1/10)
#define DEC_F     0.95122942450071400910f   // exp(-1/20)
#define CDEC_F    0.04877057549928599090f   // 1 - exp(-1/20)
#define THRESH_F  0.02f
#define A_PLUS_F  1e-4f
#define A_MINUS_F 1e-4f
#define INVB_F    0.0078125f                // 1/128, exact

#define SPLIT_A 16
#define SPLIT_I 4

typedef __nv_bfloat16 bf16;

// ---------------- state ----------------
__device__ uint32_t g_spk[(size_t)TT*BB*64];        // l1 spikes as bits (3.2MB)
__device__ float g_t1f[BB*NN];                      // rolling tr1 fp32
__device__ bf16  g_t1h[BB*NN], g_t1l[BB*NN];        // rolling tr1 splits
__device__ float g_v2 [BB*OO];
__device__ float g_vi [BB*OO];
__device__ float g_tr2[BB*OO];
__device__ float g_tri[BB*OO];
__device__ bf16  g_tr2h[BB*OO], g_tr2l[BB*OO];
__device__ bf16  g_trih[BB*OO], g_tril[BB*OO];
__device__ bf16  g_bufb[BB*DLY*OO];
__device__ float g_hw [(size_t)OO*NN];
__device__ bf16  g_hwh[(size_t)OO*NN], g_hwm[(size_t)OO*NN], g_hwl[(size_t)OO*NN];
__device__ float g_iew[OO*OO];
__device__ bf16  g_iewh[OO*OO], g_iewm[OO*OO], g_iewl[OO*OO];
__device__ float g_ediag[OO];
__device__ float g_mtr2[OO];
__device__ float g_pA[SPLIT_A*BB*OO];
__device__ float g_pI[SPLIT_I*BB*OO];
__device__ int   g_nzcnt[NN];
__device__ int   g_nzcol[(size_t)NN*NN];
__device__ float g_nzval[(size_t)NN*NN];
__device__ int   g_done;                            // gemm-done counter (reset by plast)

__device__ __forceinline__ void split3(float w, bf16& h, bf16& m, bf16& l) {
    h = __float2bfloat16(w);
    float r1 = __fadd_rn(w, -__bfloat162float(h));
    m = __float2bfloat16(r1);
    float r2 = __fadd_rn(r1, -__bfloat162float(m));
    l = __float2bfloat16(r2);
}
__device__ __forceinline__ void split2(float w, bf16& h, bf16& l) {
    h = __float2bfloat16(w);
    l = __float2bfloat16(__fadd_rn(w, -__bfloat162float(h)));
}
__device__ __forceinline__ uint32_t s2u(const void* p) {
    return (uint32_t)__cvta_generic_to_shared(p);
}
__device__ __forceinline__ void cpa16(uint32_t d, const void* s) {
    asm volatile("cp.async.ca.shared.global [%0], [%1], 16;\n" :: "r"(d), "l"(s));
}
__device__ __forceinline__ void cpa_commit_wait() {
    asm volatile("cp.async.commit_group;\n");
    asm volatile("cp.async.wait_group 0;\n");
}
__device__ __forceinline__ uint32_t packbf2(bf16 a, bf16 b) {
    __nv_bfloat162 v(a, b);
    return *(uint32_t*)&v;
}

// ---------------- init ----------------
__global__ void k_init(const float* __restrict__ hw_in,
                       const float* __restrict__ eiw_in,
                       const float* __restrict__ iew_in) {
    int i = blockIdx.x * blockDim.x + threadIdx.x;
    if (i < OO*NN) {
        float w = hw_in[i];
        g_hw[i] = w;
        split3(w, g_hwh[i], g_hwm[i], g_hwl[i]);
    }
    if (i < BB*NN) {
        g_t1f[i] = 0.f;
        bf16 z = __float2bfloat16(0.f);
        g_t1h[i] = z; g_t1l[i] = z;
    }
    if (i < BB*DLY*OO) g_bufb[i] = __float2bfloat16(0.f);
    if (i < BB*OO) {
        g_v2[i]=0.f; g_vi[i]=0.f; g_tr2[i]=0.f; g_tri[i]=0.f;
        bf16 z = __float2bfloat16(0.f);
        g_tr2h[i]=z; g_tr2l[i]=z; g_trih[i]=z; g_tril[i]=z;
    }
    if (i < OO*OO) {
        int r = i / OO, c = i - r*OO;
        float w = (r == c) ? 0.f : iew_in[i];
        g_iew[i] = w;
        split3(w, g_iewh[i], g_iewm[i], g_iewl[i]);
    }
    if (i < OO) g_ediag[i] = eiw_in[i*OO + i];
    if (i == 0) g_done = 0;
}

// ---------------- CSR build ----------------
__global__ void k_csr(const float* __restrict__ W) {
    int wid  = (blockIdx.x * blockDim.x + threadIdx.x) >> 5;
    int lane = threadIdx.x & 31;
    if (wid >= NN) return;
    int cnt = 0;
    for (int base = 0; base < NN; base += 32) {
        float w = W[wid*NN + base + lane];
        unsigned m = __ballot_sync(0xffffffffu, w != 0.f);
        if (w != 0.f) {
            int pos = cnt + __popc(m & ((1u << lane) - 1u));
            g_nzcol[(size_t)wid*NN + pos] = base + lane;
            g_nzval[(size_t)wid*NN + pos] = w;
        }
        cnt += __popc(m);
    }
    if (lane == 0) g_nzcnt[wid] = cnt;
}

// ---------------- layer 1: all T steps, spikes -> fp32 out + bitmask ----------------
__global__ __launch_bounds__(256) void k_layer1_all(const float* __restrict__ x,
                                                    float* __restrict__ out_l1) {
    int idx = blockIdx.x * 256 + threadIdx.x;
    int b = idx >> 11;
    int n = idx & (NN - 1);
    int cnt = g_nzcnt[n];
    const int*   cp = g_nzcol + (size_t)n*NN;
    const float* vp = g_nzval + (size_t)n*NN;
    const float* xb = x + (size_t)b*TT*NN;
    float v = 0.f;
    for (int t = 0; t < TT; t++) {
        const float* xr = xb + (size_t)t*NN;
        float acc = 0.f;
        for (int j = 0; j < cnt; j++) acc = fmaf(xr[cp[j]], vp[j], acc);
        v = fmaf(ALPHA_F, v, acc);
        float s = (v > THRESH_F) ? 1.f : 0.f;
        v = (v > THRESH_F) ? 0.f : v;
        out_l1[((size_t)b*TT + t)*NN + n] = s;
        unsigned m = __ballot_sync(0xffffffffu, s > 0.f);
        if ((n & 31) == 0) g_spk[((size_t)t*BB + b)*64 + (n >> 5)] = m;
    }
}

extern __shared__ __align__(16) char smem_raw[];

// ---------------- epi item (R8-identical math; item 0..63 covers 8 q) ----------------
__device__ __forceinline__ void epi_item(int item, float* __restrict__ out_l2, int t, int tm) {
    __shared__ float sh[3][32][8];
    int qb = item * 8;
    int tq = threadIdx.x & 7;
    int tb = threadIdx.x >> 3;
    int q  = qb + tq;

    float r2 = 0.f, ri = 0.f, rd = 0.f;
    for (int j = 0; j < 4; j++) {
        int b  = tb + 32*j;
        int bo = b*OO + q;
        float l1v = 0.f, io = 0.f;
        #pragma unroll
        for (int s = 0; s < SPLIT_A; s++) l1v = __fadd_rn(l1v, g_pA[(size_t)s*BB*OO + bo]);
        #pragma unroll
        for (int s = 0; s < SPLIT_I; s++) io  = __fadd_rn(io,  g_pI[(size_t)s*BB*OO + bo]);
        float v = fmaf(ALPHA_F, g_v2[bo], __fadd_rn(l1v, -io));
        float s2 = (v > THRESH_F) ? 1.f : 0.f;
        g_v2[bo] = (v > THRESH_F) ? 0.f : v;
        out_l2[((size_t)b*TT + t)*OO + q] = s2;
        float t2 = fmaf(DEC_F, g_tr2[bo], __fmul_rn(CDEC_F, s2));
        g_tr2[bo] = t2;
        { bf16 h, l; split2(t2, h, l); g_tr2h[bo] = h; g_tr2l[bo] = l; }
        float inh_in = __fmul_rn(s2, g_ediag[q]);
        float vv = fmaf(ALPHA_F, g_vi[bo], inh_in);
        float si = (vv > THRESH_F) ? 1.f : 0.f;
        g_vi[bo] = (vv > THRESH_F) ? 0.f : vv;
        g_bufb[((size_t)b*DLY + tm)*OO + q] = __float2bfloat16(si);
        float ti = fmaf(DEC_F, g_tri[bo], __fmul_rn(CDEC_F, si));
        g_tri[bo] = ti;
        { bf16 h, l; split2(ti, h, l); g_trih[bo] = h; g_tril[bo] = l; }
        r2 += t2; ri += ti; rd = fmaf(ti, t2, rd);
    }
    sh[0][tb][tq] = r2; sh[1][tb][tq] = ri; sh[2][tb][tq] = rd;
    __syncthreads();
    if (tb == 0) {
        float s2 = 0.f, si = 0.f, sd = 0.f;
        for (int g = 0; g < 32; g++) { s2 += sh[0][g][tq]; si += sh[1][g][tq]; sd += sh[2][g][tq]; }
        float m2 = s2 * INVB_F, mi = si * INVB_F;
        g_mtr2[q] = m2;
        float e = g_ediag[q];
        float dw = fmaf(A_PLUS_F, __fmul_rn(sd, INVB_F),
                        -__fmul_rn(__fmul_rn(A_MINUS_F, e), mi));
        g_ediag[q] = __fadd_rn(e, dw);
    }
}

// ---------------- launch A: gemm (320 items, m=64 tiles) + epi tail on blocks 0..63 ----------------
// item: chunk = bid >> 4, qt = bid & 7, mo = ((bid >> 3) & 1) * 64
__global__ __launch_bounds__(256) void k_gemm(float* __restrict__ out_l2, int t, int tm) {
    bf16* sA = (bf16*)smem_raw;        // [64][136]
    bf16* sB = sA + 64*136;            // [3][64][136]
    int bid = blockIdx.x;
    int tid = threadIdx.x;
    int chunk = bid >> 4, qt = bid & 7, mo = ((bid >> 3) & 1) * 64;
    const bf16 *W0, *W1, *W2;
    int wstride, k0; float* part;
    uint32_t sAu = s2u(sA), sBu = s2u(sB);
    int q0 = qt*64;

    if (chunk < SPLIT_A) {
        k0 = chunk*128;
        W0 = g_hwh; W1 = g_hwm; W2 = g_hwl; wstride = NN;
        part = g_pA + (size_t)chunk*BB*OO;
        // decode spike bits -> bf16 tile [64][128]
        int r = tid >> 2, wsel = tid & 3;
        uint32_t wbits = g_spk[((size_t)t*BB + mo + r)*64 + (k0 >> 5) + wsel];
        uint32_t* dst = (uint32_t*)(sA + r*136 + wsel*32);
        #pragma unroll
        for (int i = 0; i < 16; i++) {
            uint32_t v = (((wbits >> (2*i)) & 1u) ? 0x3F80u : 0u)
                       | (((wbits >> (2*i+1)) & 1u) ? 0x3F800000u : 0u);
            dst[i] = v;
        }
    } else {
        k0 = (chunk - SPLIT_A)*128;
        W0 = g_iewh; W1 = g_iewm; W2 = g_iewl; wstride = OO;
        part = g_pI + (size_t)(chunk - SPLIT_A)*BB*OO;
        const bf16* Asrc = g_bufb + tm*OO;
        #pragma unroll
        for (int i = 0; i < 4; i++) {
            int idx = tid + i*256;
            int r = idx >> 4, c8 = idx & 15;
            cpa16(sAu + (uint32_t)(r*136 + c8*8)*2u,
                  Asrc + (size_t)(mo + r)*((size_t)DLY*OO) + k0 + c8*8);
        }
    }
    const bf16* Ws[3] = {W0, W1, W2};
    #pragma unroll
    for (int s = 0; s < 3; s++) {
        #pragma unroll
        for (int i = 0; i < 4; i++) {
            int idx = tid + i*256;
            int r = idx >> 4, c8 = idx & 15;
            cpa16(sBu + (uint32_t)((s*64 + r)*136 + c8*8)*2u,
                  Ws[s] + (size_t)(q0 + r)*wstride + k0 + c8*8);
        }
    }
    cpa_commit_wait();
    __syncthreads();

    int w = tid >> 5, lane = tid & 31, g = lane >> 2, qi = lane & 3;
    int wm = w & 3, wn = w >> 2;
    int lr = lane & 7, lsel = lane >> 3;

    uint32_t a[8][4];
    int arow = 16*wm + lr + ((lsel & 1) ? 8 : 0);
    #pragma unroll
    for (int k16 = 0; k16 < 8; k16++) {
        int acol = k16*16 + ((lsel & 2) ? 8 : 0);
        uint32_t addr = sAu + (uint32_t)(arow*136 + acol)*2u;
        asm volatile("ldmatrix.sync.aligned.m8n8.x4.shared.b16 {%0,%1,%2,%3}, [%4];"
                     : "=r"(a[k16][0]), "=r"(a[k16][1]), "=r"(a[k16][2]), "=r"(a[k16][3])
                     : "r"(addr));
    }

    float acc[4][4];
    #pragma unroll
    for (int j = 0; j < 4; j++) { acc[j][0]=0.f; acc[j][1]=0.f; acc[j][2]=0.f; acc[j][3]=0.f; }

    int brow_base = wn*32 + lr;
    int bcol_off = (lane & 8) ? 8 : 0;
    #pragma unroll
    for (int s = 0; s < 3; s++) {
        #pragma unroll
        for (int k16 = 0; k16 < 8; k16++) {
            uint32_t bb[4][2];
            #pragma unroll
            for (int j = 0; j < 4; j++) {
                uint32_t baddr = sBu + (uint32_t)((s*64 + brow_base + j*8)*136 + k16*16 + bcol_off)*2u;
                asm volatile("ldmatrix.sync.aligned.m8n8.x2.shared.b16 {%0,%1}, [%2];"
                             : "=r"(bb[j][0]), "=r"(bb[j][1]) : "r"(baddr));
            }
            #pragma unroll
            for (int j = 0; j < 4; j++) {
                asm volatile(
                    "mma.sync.aligned.m16n8k16.row.col.f32.bf16.bf16.f32 "
                    "{%0,%1,%2,%3},{%4,%5,%6,%7},{%8,%9},{%0,%1,%2,%3};\n"
                    : "+f"(acc[j][0]), "+f"(acc[j][1]), "+f"(acc[j][2]), "+f"(acc[j][3])
                    : "r"(a[k16][0]), "r"(a[k16][1]), "r"(a[k16][2]), "r"(a[k16][3]),
                      "r"(bb[j][0]), "r"(bb[j][1]));
            }
        }
    }
    int m0 = mo + 16*wm + g;
    #pragma unroll
    for (int j = 0; j < 4; j++) {
        int qc = q0 + wn*32 + j*8 + qi*2;
        *(float2*)(part + (size_t)m0*OO + qc)       = make_float2(acc[j][0], acc[j][1]);
        *(float2*)(part + (size_t)(m0 + 8)*OO + qc) = make_float2(acc[j][2], acc[j][3]);
    }

    // signal: this block's partials are visible
    __syncthreads();
    if (tid == 0) { __threadfence(); atomicAdd(&g_done, 1); }

    // ---- tr1 rolling update tail: blocks 0..255, 1024 elements each ----
    if (bid < 256) {
        int base = bid*1024 + tid*4;
        int b = base >> 11, n = base & (NN - 1);
        uint32_t wbits = g_spk[((size_t)t*BB + b)*64 + (n >> 5)];
        int sh = n & 31;
        float4 tr = *(float4*)(g_t1f + base);
        float s0 = ((wbits >> (sh+0)) & 1u) ? 1.f : 0.f;
        float s1 = ((wbits >> (sh+1)) & 1u) ? 1.f : 0.f;
        float s2 = ((wbits >> (sh+2)) & 1u) ? 1.f : 0.f;
        float s3 = ((wbits >> (sh+3)) & 1u) ? 1.f : 0.f;
        tr.x = fmaf(DEC_F, tr.x, __fmul_rn(CDEC_F, s0));
        tr.y = fmaf(DEC_F, tr.y, __fmul_rn(CDEC_F, s1));
        tr.z = fmaf(DEC_F, tr.z, __fmul_rn(CDEC_F, s2));
        tr.w = fmaf(DEC_F, tr.w, __fmul_rn(CDEC_F, s3));
        *(float4*)(g_t1f + base) = tr;
        bf16 h0,l0,h1,l1,h2,l2,h3,l3;
        split2(tr.x, h0, l0); split2(tr.y, h1, l1);
        split2(tr.z, h2, l2); split2(tr.w, h3, l3);
        *(uint2*)(g_t1h + base) = make_uint2(packbf2(h0, h1), packbf2(h2, h3));
        *(uint2*)(g_t1l + base) = make_uint2(packbf2(l0, l1), packbf2(l2, l3));
    }

    // ---- epi tail on blocks 0..63: wait for ALL gemm items, then run epilogue ----
    if (bid < 64) {
        if (tid == 0) {
            while (*((volatile int*)&g_done) < 320) __nanosleep(64);
            __threadfence();
        }
        __syncthreads();
        epi_item(bid, out_l2, t, tm);
    }
}

// ---------------- launch B: plast (R8 body), resets g_done ----------------
// grid (40, 8): bx 0..31 hw p-tiles, 32..39 iew; by q-tiles of 64
__global__ __launch_bounds__(256) void k_plast() {
    int bx = blockIdx.x, by = blockIdx.y;
    int tid = threadIdx.x;
    if (bx == 0 && by == 0 && tid == 0) g_done = 0;   // reset for next step's gemm

    bf16* sAh = (bf16*)smem_raw;        // [b=128][72] (tr2 hi)
    bf16* sAl = sAh + 128*72;
    bf16* sB0 = sAl + 128*72;           // [b=128][72] (pre hi)
    bf16* sB1 = sB0 + 128*72;
    int mode = (bx >= 32);
    int p0 = (mode ? (bx - 32) : bx) * 64;
    int q0 = by * 64;
    const bf16* preh = mode ? g_trih : g_t1h;
    const bf16* prel = mode ? g_tril : g_t1l;
    int P = mode ? OO : NN;
    float* W = mode ? g_iew : g_hw;
    bf16 *Wh = mode ? g_iewh : g_hwh, *Wm = mode ? g_iewm : g_hwm, *Wl = mode ? g_iewl : g_hwl;

    uint32_t sAhu = s2u(sAh), sAlu = s2u(sAl), sB0u = s2u(sB0), sB1u = s2u(sB1);

    #pragma unroll
    for (int i = 0; i < 4; i++) {
        int idx = tid + i*256;
        int b = idx >> 3, c8 = idx & 7;
        uint32_t so = (uint32_t)(b*72 + c8*8)*2u;
        cpa16(sAhu + so, g_tr2h + b*OO + q0 + c8*8);
        cpa16(sAlu + so, g_tr2l + b*OO + q0 + c8*8);
        cpa16(sB0u + so, preh + (size_t)b*P + p0 + c8*8);
        cpa16(sB1u + so, prel + (size_t)b*P + p0 + c8*8);
    }
    cpa_commit_wait();
    __syncthreads();

    int w = tid >> 5, lane = tid & 31, g = lane >> 2, qi = lane & 3;
    int r8 = lane & 7, sel = lane >> 3;

    float acc[4][4];
    #pragma unroll
    for (int mi = 0; mi < 4; mi++) { acc[mi][0]=0.f; acc[mi][1]=0.f; acc[mi][2]=0.f; acc[mi][3]=0.f; }

    #pragma unroll
    for (int k16 = 0; k16 < 8; k16++) {
        int kb16 = k16*16;
        int rrB = kb16 + ((sel & 1) ? 8 : 0) + r8;
        uint32_t bo = (uint32_t)(rrB*72 + w*8)*2u;
        uint32_t bh0, bh1, bl0, bl1;
        asm volatile("ldmatrix.sync.aligned.m8n8.x2.trans.shared.b16 {%0,%1}, [%2];"
                     : "=r"(bh0), "=r"(bh1) : "r"(sB0u + bo));
        asm volatile("ldmatrix.sync.aligned.m8n8.x2.trans.shared.b16 {%0,%1}, [%2];"
                     : "=r"(bl0), "=r"(bl1) : "r"(sB1u + bo));
        int rrA = kb16 + ((sel & 2) ? 8 : 0) + r8;
        #pragma unroll
        for (int mi = 0; mi < 4; mi++) {
            int cc = mi*16 + ((sel & 1) ? 8 : 0);
            uint32_t ao = (uint32_t)(rrA*72 + cc)*2u;
            #pragma unroll
            for (int as = 0; as < 2; as++) {
                uint32_t a0, a1, a2, a3;
                asm volatile("ldmatrix.sync.aligned.m8n8.x4.trans.shared.b16 {%0,%1,%2,%3}, [%4];"
                             : "=r"(a0), "=r"(a1), "=r"(a2), "=r"(a3)
                             : "r"((as ? sAlu : sAhu) + ao));
                asm volatile(
                    "mma.sync.aligned.m16n8k16.row.col.f32.bf16.bf16.f32 "
                    "{%0,%1,%2,%3},{%4,%5,%6,%7},{%8,%9},{%0,%1,%2,%3};\n"
                    : "+f"(acc[mi][0]), "+f"(acc[mi][1]), "+f"(acc[mi][2]), "+f"(acc[mi][3])
                    : "r"(a0), "r"(a1), "r"(a2), "r"(a3), "r"(bh0), "r"(bh1));
                asm volatile(
                    "mma.sync.aligned.m16n8k16.row.col.f32.bf16.bf16.f32 "
                    "{%0,%1,%2,%3},{%4,%5,%6,%7},{%8,%9},{%0,%1,%2,%3};\n"
                    : "+f"(acc[mi][0]), "+f"(acc[mi][1]), "+f"(acc[mi][2]), "+f"(acc[mi][3])
                    : "r"(a0), "r"(a1), "r"(a2), "r"(a3), "r"(bl0), "r"(bl1));
            }
        }
    }

    int pc = p0 + w*8 + qi*2;
    #pragma unroll
    for (int mi = 0; mi < 4; mi++) {
        #pragma unroll
        for (int half = 0; half < 2; half++) {
            int qq = q0 + mi*16 + g + half*8;
            float h0 = acc[mi][half*2 + 0], h1 = acc[mi][half*2 + 1];
            float mean = g_mtr2[qq];
            size_t wbase = (size_t)qq*P + pc;
            float2 wv = *(float2*)(W + wbase);
            float dw0 = fmaf(A_PLUS_F, __fmul_rn(h0, INVB_F),
                             -__fmul_rn(__fmul_rn(A_MINUS_F, wv.x), mean));
            float dw1 = fmaf(A_PLUS_F, __fmul_rn(h1, INVB_F),
                             -__fmul_rn(__fmul_rn(A_MINUS_F, wv.y), mean));
            float nw0 = __fadd_rn(wv.x, dw0);
            float nw1 = __fadd_rn(wv.y, dw1);
            if (mode && qq == pc)     nw0 = 0.f;
            if (mode && qq == pc + 1) nw1 = 0.f;
            *(float2*)(W + wbase) = make_float2(nw0, nw1);
            bf16 h, m, l, h2, m2, l2;
            split3(nw0, h, m, l);
            split3(nw1, h2, m2, l2);
            *(__nv_bfloat162*)(Wh + wbase) = __nv_bfloat162(h, h2);
            *(__nv_bfloat162*)(Wm + wbase) = __nv_bfloat162(m, m2);
            *(__nv_bfloat162*)(Wl + wbase) = __nv_bfloat162(l, l2);
        }
    }
}

// ---------------- launch ----------------
extern "C" void kernel_launch(void* const* d_in, const int* in_sizes, int n_in,
                              void* d_out, int out_size) {
    const float* x      = (const float*)d_in[0];
    const float* win    = (const float*)d_in[1];
    const float* hw_in  = (const float*)d_in[2];
    const float* eiw_in = (const float*)d_in[3];
    const float* iew_in = (const float*)d_in[4];
    float* out_l1 = (float*)d_out;
    float* out_l2 = out_l1 + (size_t)BB*TT*NN;

    const int sm_gemm  = 4 * 64*136 * 2;   // 69632
    const int sm_plast = 4 * 128*72 * 2;   // 73728
    cudaFuncSetAttribute(k_gemm,  cudaFuncAttributeMaxDynamicSharedMemorySize, sm_gemm);
    cudaFuncSetAttribute(k_plast, cudaFuncAttributeMaxDynamicSharedMemorySize, sm_plast);

    k_init<<<(OO*NN)/256, 256>>>(hw_in, eiw_in, iew_in);
    k_csr<<<256, 256>>>(win);
    k_layer1_all<<<(BB*NN)/256, 256>>>(x, out_l1);

    for (int t = 0; t < TT; t++) {
        int tm = t % DLY;
        k_gemm<<<320, 256, sm_gemm>>>(out_l2, t, tm);
        k_plast<<<dim3(40, 8), 256, sm_plast>>>();
    }
}

// round 17
// speedup vs baseline: 1.0972x; 1.0227x over previous
#include <cuda_runtime.h>
#include <cuda_bf16.h>
#include <cstdint>

#define BB 128
#define TT 100
#define NN 2048
#define OO 512
#define DLY 10

#define ALPHA_F   0.90483741803595957316f   // exp(-1/10)
#define DEC_F     0.95122942450071400910f   // exp(-1/20)
#define CDEC_F    0.04877057549928599090f   // 1 - exp(-1/20)
#define THRESH_F  0.02f
#define A_PLUS_F  1e-4f
#define A_MINUS_F 1e-4f
#define INVB_F    0.0078125f                // 1/128, exact

#define SPLIT_A 16
#define SPLIT_I 4

typedef __nv_bfloat16 bf16;

// ---------------- state ----------------
__device__ uint32_t g_spk[(size_t)TT*BB*64];        // l1 spikes as bits (3.2MB)
__device__ float g_t1f[BB*NN];                      // rolling tr1 fp32
__device__ bf16  g_t1h[BB*NN], g_t1l[BB*NN];        // rolling tr1 splits
__device__ float g_v2 [BB*OO];
__device__ float g_vi [BB*OO];
__device__ float g_tr2[BB*OO];
__device__ float g_tri[BB*OO];
__device__ bf16  g_tr2h[BB*OO], g_tr2l[BB*OO];
__device__ bf16  g_trih[BB*OO], g_tril[BB*OO];
__device__ bf16  g_bufb[BB*DLY*OO];
__device__ float g_hw [(size_t)OO*NN];
__device__ bf16  g_hwh[(size_t)OO*NN], g_hwm[(size_t)OO*NN], g_hwl[(size_t)OO*NN];
__device__ float g_iew[OO*OO];
__device__ bf16  g_iewh[OO*OO], g_iewm[OO*OO], g_iewl[OO*OO];
__device__ float g_ediag[OO];
__device__ float g_mtr2[OO];
__device__ float g_pA[SPLIT_A*BB*OO];
__device__ float g_pI[SPLIT_I*BB*OO];
__device__ int   g_nzcnt[NN];
__device__ int   g_nzcol[(size_t)NN*NN];
__device__ float g_nzval[(size_t)NN*NN];

__device__ __forceinline__ void split3(float w, bf16& h, bf16& m, bf16& l) {
    h = __float2bfloat16(w);
    float r1 = __fadd_rn(w, -__bfloat162float(h));
    m = __float2bfloat16(r1);
    float r2 = __fadd_rn(r1, -__bfloat162float(m));
    l = __float2bfloat16(r2);
}
__device__ __forceinline__ void split2(float w, bf16& h, bf16& l) {
    h = __float2bfloat16(w);
    l = __float2bfloat16(__fadd_rn(w, -__bfloat162float(h)));
}
__device__ __forceinline__ uint32_t s2u(const void* p) {
    return (uint32_t)__cvta_generic_to_shared(p);
}
__device__ __forceinline__ void cpa16(uint32_t d, const void* s) {
    asm volatile("cp.async.ca.shared.global [%0], [%1], 16;\n" :: "r"(d), "l"(s));
}
__device__ __forceinline__ void cpa_commit() {
    asm volatile("cp.async.commit_group;\n");
}
template <int N>
__device__ __forceinline__ void cpa_wait() {
    asm volatile("cp.async.wait_group %0;\n" :: "n"(N));
}
__device__ __forceinline__ uint32_t packbf2(bf16 a, bf16 b) {
    __nv_bfloat162 v(a, b);
    return *(uint32_t*)&v;
}

// ---------------- init ----------------
__global__ void k_init(const float* __restrict__ hw_in,
                       const float* __restrict__ eiw_in,
                       const float* __restrict__ iew_in) {
    int i = blockIdx.x * blockDim.x + threadIdx.x;
    if (i < OO*NN) {
        float w = hw_in[i];
        g_hw[i] = w;
        split3(w, g_hwh[i], g_hwm[i], g_hwl[i]);
    }
    if (i < BB*NN) {
        g_t1f[i] = 0.f;
        bf16 z = __float2bfloat16(0.f);
        g_t1h[i] = z; g_t1l[i] = z;
    }
    if (i < BB*DLY*OO) g_bufb[i] = __float2bfloat16(0.f);
    if (i < BB*OO) {
        g_v2[i]=0.f; g_vi[i]=0.f; g_tr2[i]=0.f; g_tri[i]=0.f;
        bf16 z = __float2bfloat16(0.f);
        g_tr2h[i]=z; g_tr2l[i]=z; g_trih[i]=z; g_tril[i]=z;
    }
    if (i < OO*OO) {
        int r = i / OO, c = i - r*OO;
        float w = (r == c) ? 0.f : iew_in[i];
        g_iew[i] = w;
        split3(w, g_iewh[i], g_iewm[i], g_iewl[i]);
    }
    if (i < OO) g_ediag[i] = eiw_in[i*OO + i];
}

// ---------------- CSR build ----------------
__global__ void k_csr(const float* __restrict__ W) {
    int wid  = (blockIdx.x * blockDim.x + threadIdx.x) >> 5;
    int lane = threadIdx.x & 31;
    if (wid >= NN) return;
    int cnt = 0;
    for (int base = 0; base < NN; base += 32) {
        float w = W[wid*NN + base + lane];
        unsigned m = __ballot_sync(0xffffffffu, w != 0.f);
        if (w != 0.f) {
            int pos = cnt + __popc(m & ((1u << lane) - 1u));
            g_nzcol[(size_t)wid*NN + pos] = base + lane;
            g_nzval[(size_t)wid*NN + pos] = w;
        }
        cnt += __popc(m);
    }
    if (lane == 0) g_nzcnt[wid] = cnt;
}

// ---------------- layer 1: all T steps, spikes -> fp32 out + bitmask ----------------
__global__ __launch_bounds__(256) void k_layer1_all(const float* __restrict__ x,
                                                    float* __restrict__ out_l1) {
    int idx = blockIdx.x * 256 + threadIdx.x;
    int b = idx >> 11;
    int n = idx & (NN - 1);
    int cnt = g_nzcnt[n];
    const int*   cp = g_nzcol + (size_t)n*NN;
    const float* vp = g_nzval + (size_t)n*NN;
    const float* xb = x + (size_t)b*TT*NN;
    float v = 0.f;
    for (int t = 0; t < TT; t++) {
        const float* xr = xb + (size_t)t*NN;
        float acc = 0.f;
        for (int j = 0; j < cnt; j++) acc = fmaf(xr[cp[j]], vp[j], acc);
        v = fmaf(ALPHA_F, v, acc);
        float s = (v > THRESH_F) ? 1.f : 0.f;
        v = (v > THRESH_F) ? 0.f : v;
        out_l1[((size_t)b*TT + t)*NN + n] = s;
        unsigned m = __ballot_sync(0xffffffffu, s > 0.f);
        if ((n & 31) == 0) g_spk[((size_t)t*BB + b)*64 + (n >> 5)] = m;
    }
}

extern __shared__ __align__(16) char smem_raw[];

// ---------------- gemm: 320 items (m=64), staged split-pass pipeline ----------------
// item: chunk = bid >> 4, qt = bid & 7, mo = ((bid >> 3) & 1) * 64. Blocks <256: tr1 tail.
__global__ __launch_bounds__(256) void k_gemm(int t, int tm) {
    bf16* sA = (bf16*)smem_raw;        // [64][136]
    bf16* sB = sA + 64*136;            // [3][64][136]
    int bid = blockIdx.x;
    int tid = threadIdx.x;
    int chunk = bid >> 4, qt = bid & 7, mo = ((bid >> 3) & 1) * 64;
    const bf16 *W0, *W1, *W2;
    int wstride, k0; float* part;
    uint32_t sAu = s2u(sA), sBu = s2u(sB);
    int q0 = qt*64;

    if (chunk < SPLIT_A) {
        k0 = chunk*128;
        W0 = g_hwh; W1 = g_hwm; W2 = g_hwl; wstride = NN;
        part = g_pA + (size_t)chunk*BB*OO;
    } else {
        k0 = (chunk - SPLIT_A)*128;
        W0 = g_iewh; W1 = g_iewm; W2 = g_iewl; wstride = OO;
        part = g_pI + (size_t)(chunk - SPLIT_A)*BB*OO;
        const bf16* Asrc = g_bufb + tm*OO;
        #pragma unroll
        for (int i = 0; i < 4; i++) {
            int idx = tid + i*256;
            int r = idx >> 4, c8 = idx & 15;
            cpa16(sAu + (uint32_t)(r*136 + c8*8)*2u,
                  Asrc + (size_t)(mo + r)*((size_t)DLY*OO) + k0 + c8*8);
        }
    }
    cpa_commit();                                   // group: A (empty for hw path)
    const bf16* Ws[3] = {W0, W1, W2};
    #pragma unroll
    for (int s = 0; s < 3; s++) {
        #pragma unroll
        for (int i = 0; i < 4; i++) {
            int idx = tid + i*256;
            int r = idx >> 4, c8 = idx & 15;
            cpa16(sBu + (uint32_t)((s*64 + r)*136 + c8*8)*2u,
                  Ws[s] + (size_t)(q0 + r)*wstride + k0 + c8*8);
        }
        cpa_commit();                               // one group per split tile
    }
    if (chunk < SPLIT_A) {
        // decode spike bits -> bf16 tile [64][128] (overlaps with in-flight cp.async)
        int r = tid >> 2, wsel = tid & 3;
        uint32_t wbits = g_spk[((size_t)t*BB + mo + r)*64 + (k0 >> 5) + wsel];
        uint32_t* dst = (uint32_t*)(sA + r*136 + wsel*32);
        #pragma unroll
        for (int i = 0; i < 16; i++) {
            uint32_t v = (((wbits >> (2*i)) & 1u) ? 0x3F80u : 0u)
                       | (((wbits >> (2*i+1)) & 1u) ? 0x3F800000u : 0u);
            dst[i] = v;
        }
    }
    cpa_wait<2>();                                  // A + B0 complete
    __syncthreads();

    int w = tid >> 5, lane = tid & 31, g = lane >> 2, qi = lane & 3;
    int wm = w & 3, wn = w >> 2;
    int lr = lane & 7, lsel = lane >> 3;

    uint32_t a[8][4];
    int arow = 16*wm + lr + ((lsel & 1) ? 8 : 0);
    #pragma unroll
    for (int k16 = 0; k16 < 8; k16++) {
        int acol = k16*16 + ((lsel & 2) ? 8 : 0);
        uint32_t addr = sAu + (uint32_t)(arow*136 + acol)*2u;
        asm volatile("ldmatrix.sync.aligned.m8n8.x4.shared.b16 {%0,%1,%2,%3}, [%4];"
                     : "=r"(a[k16][0]), "=r"(a[k16][1]), "=r"(a[k16][2]), "=r"(a[k16][3])
                     : "r"(addr));
    }

    float acc[4][4];
    #pragma unroll
    for (int j = 0; j < 4; j++) { acc[j][0]=0.f; acc[j][1]=0.f; acc[j][2]=0.f; acc[j][3]=0.f; }

    int brow_base = wn*32 + lr;
    int bcol_off = (lane & 8) ? 8 : 0;
    #pragma unroll
    for (int s = 0; s < 3; s++) {
        if (s == 1) { cpa_wait<1>(); __syncthreads(); }
        if (s == 2) { cpa_wait<0>(); __syncthreads(); }
        #pragma unroll
        for (int k16 = 0; k16 < 8; k16++) {
            uint32_t bb[4][2];
            #pragma unroll
            for (int j = 0; j < 4; j++) {
                uint32_t baddr = sBu + (uint32_t)((s*64 + brow_base + j*8)*136 + k16*16 + bcol_off)*2u;
                asm volatile("ldmatrix.sync.aligned.m8n8.x2.shared.b16 {%0,%1}, [%2];"
                             : "=r"(bb[j][0]), "=r"(bb[j][1]) : "r"(baddr));
            }
            #pragma unroll
            for (int j = 0; j < 4; j++) {
                asm volatile(
                    "mma.sync.aligned.m16n8k16.row.col.f32.bf16.bf16.f32 "
                    "{%0,%1,%2,%3},{%4,%5,%6,%7},{%8,%9},{%0,%1,%2,%3};\n"
                    : "+f"(acc[j][0]), "+f"(acc[j][1]), "+f"(acc[j][2]), "+f"(acc[j][3])
                    : "r"(a[k16][0]), "r"(a[k16][1]), "r"(a[k16][2]), "r"(a[k16][3]),
                      "r"(bb[j][0]), "r"(bb[j][1]));
            }
        }
    }
    int m0 = mo + 16*wm + g;
    #pragma unroll
    for (int j = 0; j < 4; j++) {
        int qc = q0 + wn*32 + j*8 + qi*2;
        *(float2*)(part + (size_t)m0*OO + qc)       = make_float2(acc[j][0], acc[j][1]);
        *(float2*)(part + (size_t)(m0 + 8)*OO + qc) = make_float2(acc[j][2], acc[j][3]);
    }

    // ---- tr1 rolling update tail: blocks 0..255, 1024 elements each ----
    if (bid < 256) {
        int base = bid*1024 + tid*4;
        int b = base >> 11, n = base & (NN - 1);
        uint32_t wbits = g_spk[((size_t)t*BB + b)*64 + (n >> 5)];
        int sh = n & 31;
        float4 tr = *(float4*)(g_t1f + base);
        float s0 = ((wbits >> (sh+0)) & 1u) ? 1.f : 0.f;
        float s1 = ((wbits >> (sh+1)) & 1u) ? 1.f : 0.f;
        float s2 = ((wbits >> (sh+2)) & 1u) ? 1.f : 0.f;
        float s3 = ((wbits >> (sh+3)) & 1u) ? 1.f : 0.f;
        tr.x = fmaf(DEC_F, tr.x, __fmul_rn(CDEC_F, s0));
        tr.y = fmaf(DEC_F, tr.y, __fmul_rn(CDEC_F, s1));
        tr.z = fmaf(DEC_F, tr.z, __fmul_rn(CDEC_F, s2));
        tr.w = fmaf(DEC_F, tr.w, __fmul_rn(CDEC_F, s3));
        *(float4*)(g_t1f + base) = tr;
        bf16 h0,l0,h1,l1,h2,l2,h3,l3;
        split2(tr.x, h0, l0); split2(tr.y, h1, l1);
        split2(tr.z, h2, l2); split2(tr.w, h3, l3);
        *(uint2*)(g_t1h + base) = make_uint2(packbf2(h0, h1), packbf2(h2, h3));
        *(uint2*)(g_t1l + base) = make_uint2(packbf2(l0, l1), packbf2(l2, l3));
    }
}

// ---------------- epi: 64 blocks, R8-identical math ----------------
__global__ __launch_bounds__(256) void k_epi(float* __restrict__ out_l2, int t, int tm) {
    __shared__ float sh[3][32][8];
    int qb = blockIdx.x * 8;
    int tq = threadIdx.x & 7;
    int tb = threadIdx.x >> 3;
    int q  = qb + tq;

    float r2 = 0.f, ri = 0.f, rd = 0.f;
    for (int j = 0; j < 4; j++) {
        int b  = tb + 32*j;
        int bo = b*OO + q;
        float l1v = 0.f, io = 0.f;
        #pragma unroll
        for (int s = 0; s < SPLIT_A; s++) l1v = __fadd_rn(l1v, g_pA[(size_t)s*BB*OO + bo]);
        #pragma unroll
        for (int s = 0; s < SPLIT_I; s++) io  = __fadd_rn(io,  g_pI[(size_t)s*BB*OO + bo]);
        float v = fmaf(ALPHA_F, g_v2[bo], __fadd_rn(l1v, -io));
        float s2 = (v > THRESH_F) ? 1.f : 0.f;
        g_v2[bo] = (v > THRESH_F) ? 0.f : v;
        out_l2[((size_t)b*TT + t)*OO + q] = s2;
        float t2 = fmaf(DEC_F, g_tr2[bo], __fmul_rn(CDEC_F, s2));
        g_tr2[bo] = t2;
        { bf16 h, l; split2(t2, h, l); g_tr2h[bo] = h; g_tr2l[bo] = l; }
        float inh_in = __fmul_rn(s2, g_ediag[q]);
        float vv = fmaf(ALPHA_F, g_vi[bo], inh_in);
        float si = (vv > THRESH_F) ? 1.f : 0.f;
        g_vi[bo] = (vv > THRESH_F) ? 0.f : vv;
        g_bufb[((size_t)b*DLY + tm)*OO + q] = __float2bfloat16(si);
        float ti = fmaf(DEC_F, g_tri[bo], __fmul_rn(CDEC_F, si));
        g_tri[bo] = ti;
        { bf16 h, l; split2(ti, h, l); g_trih[bo] = h; g_tril[bo] = l; }
        r2 += t2; ri += ti; rd = fmaf(ti, t2, rd);
    }
    sh[0][tb][tq] = r2; sh[1][tb][tq] = ri; sh[2][tb][tq] = rd;
    __syncthreads();
    if (tb == 0) {
        float s2 = 0.f, si = 0.f, sd = 0.f;
        for (int g = 0; g < 32; g++) { s2 += sh[0][g][tq]; si += sh[1][g][tq]; sd += sh[2][g][tq]; }
        float m2 = s2 * INVB_F, mi = si * INVB_F;
        g_mtr2[q] = m2;
        float e = g_ediag[q];
        float dw = fmaf(A_PLUS_F, __fmul_rn(sd, INVB_F),
                        -__fmul_rn(__fmul_rn(A_MINUS_F, e), mi));
        g_ediag[q] = __fadd_rn(e, dw);
    }
}

// ---------------- plast: 40x8 grid (R8 body), writes fp32 + splits ----------------
__global__ __launch_bounds__(256) void k_plast() {
    int bx = blockIdx.x, by = blockIdx.y;
    int tid = threadIdx.x;

    bf16* sAh = (bf16*)smem_raw;        // [b=128][72] (tr2 hi)
    bf16* sAl = sAh + 128*72;
    bf16* sB0 = sAl + 128*72;           // [b=128][72] (pre hi)
    bf16* sB1 = sB0 + 128*72;
    int mode = (bx >= 32);
    int p0 = (mode ? (bx - 32) : bx) * 64;
    int q0 = by * 64;
    const bf16* preh = mode ? g_trih : g_t1h;
    const bf16* prel = mode ? g_tril : g_t1l;
    int P = mode ? OO : NN;
    float* W = mode ? g_iew : g_hw;
    bf16 *Wh = mode ? g_iewh : g_hwh, *Wm = mode ? g_iewm : g_hwm, *Wl = mode ? g_iewl : g_hwl;

    uint32_t sAhu = s2u(sAh), sAlu = s2u(sAl), sB0u = s2u(sB0), sB1u = s2u(sB1);

    #pragma unroll
    for (int i = 0; i < 4; i++) {
        int idx = tid + i*256;
        int b = idx >> 3, c8 = idx & 7;
        uint32_t so = (uint32_t)(b*72 + c8*8)*2u;
        cpa16(sAhu + so, g_tr2h + b*OO + q0 + c8*8);
        cpa16(sAlu + so, g_tr2l + b*OO + q0 + c8*8);
        cpa16(sB0u + so, preh + (size_t)b*P + p0 + c8*8);
        cpa16(sB1u + so, prel + (size_t)b*P + p0 + c8*8);
    }
    cpa_commit();
    cpa_wait<0>();
    __syncthreads();

    int w = tid >> 5, lane = tid & 31, g = lane >> 2, qi = lane & 3;
    int r8 = lane & 7, sel = lane >> 3;

    float acc[4][4];
    #pragma unroll
    for (int mi = 0; mi < 4; mi++) { acc[mi][0]=0.f; acc[mi][1]=0.f; acc[mi][2]=0.f; acc[mi][3]=0.f; }

    #pragma unroll
    for (int k16 = 0; k16 < 8; k16++) {
        int kb16 = k16*16;
        int rrB = kb16 + ((sel & 1) ? 8 : 0) + r8;
        uint32_t bo = (uint32_t)(rrB*72 + w*8)*2u;
        uint32_t bh0, bh1, bl0, bl1;
        asm volatile("ldmatrix.sync.aligned.m8n8.x2.trans.shared.b16 {%0,%1}, [%2];"
                     : "=r"(bh0), "=r"(bh1) : "r"(sB0u + bo));
        asm volatile("ldmatrix.sync.aligned.m8n8.x2.trans.shared.b16 {%0,%1}, [%2];"
                     : "=r"(bl0), "=r"(bl1) : "r"(sB1u + bo));
        int rrA = kb16 + ((sel & 2) ? 8 : 0) + r8;
        #pragma unroll
        for (int mi = 0; mi < 4; mi++) {
            int cc = mi*16 + ((sel & 1) ? 8 : 0);
            uint32_t ao = (uint32_t)(rrA*72 + cc)*2u;
            #pragma unroll
            for (int as = 0; as < 2; as++) {
                uint32_t a0, a1, a2, a3;
                asm volatile("ldmatrix.sync.aligned.m8n8.x4.trans.shared.b16 {%0,%1,%2,%3}, [%4];"
                             : "=r"(a0), "=r"(a1), "=r"(a2), "=r"(a3)
                             : "r"((as ? sAlu : sAhu) + ao));
                asm volatile(
                    "mma.sync.aligned.m16n8k16.row.col.f32.bf16.bf16.f32 "
                    "{%0,%1,%2,%3},{%4,%5,%6,%7},{%8,%9},{%0,%1,%2,%3};\n"
                    : "+f"(acc[mi][0]), "+f"(acc[mi][1]), "+f"(acc[mi][2]), "+f"(acc[mi][3])
                    : "r"(a0), "r"(a1), "r"(a2), "r"(a3), "r"(bh0), "r"(bh1));
                asm volatile(
                    "mma.sync.aligned.m16n8k16.row.col.f32.bf16.bf16.f32 "
                    "{%0,%1,%2,%3},{%4,%5,%6,%7},{%8,%9},{%0,%1,%2,%3};\n"
                    : "+f"(acc[mi][0]), "+f"(acc[mi][1]), "+f"(acc[mi][2]), "+f"(acc[mi][3])
                    : "r"(a0), "r"(a1), "r"(a2), "r"(a3), "r"(bl0), "r"(bl1));
            }
        }
    }

    int pc = p0 + w*8 + qi*2;
    #pragma unroll
    for (int mi = 0; mi < 4; mi++) {
        #pragma unroll
        for (int half = 0; half < 2; half++) {
            int qq = q0 + mi*16 + g + half*8;
            float h0 = acc[mi][half*2 + 0], h1 = acc[mi][half*2 + 1];
            float mean = g_mtr2[qq];
            size_t wbase = (size_t)qq*P + pc;
            float2 wv = *(float2*)(W + wbase);
            float dw0 = fmaf(A_PLUS_F, __fmul_rn(h0, INVB_F),
                             -__fmul_rn(__fmul_rn(A_MINUS_F, wv.x), mean));
            float dw1 = fmaf(A_PLUS_F, __fmul_rn(h1, INVB_F),
                             -__fmul_rn(__fmul_rn(A_MINUS_F, wv.y), mean));
            float nw0 = __fadd_rn(wv.x, dw0);
            float nw1 = __fadd_rn(wv.y, dw1);
            if (mode && qq == pc)     nw0 = 0.f;
            if (mode && qq == pc + 1) nw1 = 0.f;
            *(float2*)(W + wbase) = make_float2(nw0, nw1);
            bf16 h, m, l, h2, m2, l2;
            split3(nw0, h, m, l);
            split3(nw1, h2, m2, l2);
            *(__nv_bfloat162*)(Wh + wbase) = __nv_bfloat162(h, h2);
            *(__nv_bfloat162*)(Wm + wbase) = __nv_bfloat162(m, m2);
            *(__nv_bfloat162*)(Wl + wbase) = __nv_bfloat162(l, l2);
        }
    }
}

// ---------------- launch ----------------
extern "C" void kernel_launch(void* const* d_in, const int* in_sizes, int n_in,
                              void* d_out, int out_size) {
    const float* x      = (const float*)d_in[0];
    const float* win    = (const float*)d_in[1];
    const float* hw_in  = (const float*)d_in[2];
    const float* eiw_in = (const float*)d_in[3];
    const float* iew_in = (const float*)d_in[4];
    float* out_l1 = (float*)d_out;
    float* out_l2 = out_l1 + (size_t)BB*TT*NN;

    const int sm_gemm  = 4 * 64*136 * 2;   // 69632
    const int sm_plast = 4 * 128*72 * 2;   // 73728
    cudaFuncSetAttribute(k_gemm,  cudaFuncAttributeMaxDynamicSharedMemorySize, sm_gemm);
    cudaFuncSetAttribute(k_plast, cudaFuncAttributeMaxDynamicSharedMemorySize, sm_plast);

    k_init<<<(OO*NN)/256, 256>>>(hw_in, eiw_in, iew_in);
    k_csr<<<256, 256>>>(win);
    k_layer1_all<<<(BB*NN)/256, 256>>>(x, out_l1);

    for (int t = 0; t < TT; t++) {
        int tm = t % DLY;
        k_gemm<<<320, 256, sm_gemm>>>(t, tm);
        k_epi<<<64, 256>>>(out_l2, t, tm);
        k_plast<<<dim3(40, 8), 256, sm_plast>>>();
    }
}